// round 3
// baseline (speedup 1.0000x reference)
#include <cuda_runtime.h>
#include <math.h>
#include <stdint.h>

// Problem dims
#define Bn   8
#define Sn   256
#define Hn   768
#define Ln   20
#define LSn  8
#define En   300
#define BSn  2048            // B*S
#define MTOT 40960           // B*S*L
#define KF   1536            // fused GEMM K (W5c|W5d)
#define NEGV (-10000.0f)

// ---------------- scratch (static device globals; no allocs allowed) ----------------
__device__ __align__(16) float g_tkn[BSn * Hn];            // 6 MB
__device__ __align__(16) float g_lab[Ln * LSn * Hn];       // 0.5 MB
__device__ __align__(16) float g_T1[BSn * Hn];             // 6 MB   = tkn @ W5a^T
__device__ __align__(16) float g_Lab2[Ln * LSn * Hn];      // 0.5 MB = lab @ W5b^T
__device__ __align__(16) float g_scores[BSn * Ln * LSn];   // 1.3 MB
__device__ __align__(16) float g_a[MTOT * LSn];            // 1.3 MB  softmax probs over t
__device__ __align__(16) float g_bin[MTOT];                // 0.16 MB
__device__ __align__(16) float g_q2c[Bn * Ln * Hn];        // 0.5 MB
__device__ __align__(16) float g_Af[(size_t)MTOT * KF];    // 252 MB  fused A operand

// ---------------------------------------------------------------------------
// Generic guarded SGEMM: C[M,N] = A[M,K] * B[N,K]^T   (64x64x16 tile, 256 thr)
// ---------------------------------------------------------------------------
__global__ __launch_bounds__(256) void sgemm_abt64(
    const float* __restrict__ A, int lda,
    const float* __restrict__ Bm, int ldb,
    float* __restrict__ C, int ldc,
    int M, int N, int K)
{
    __shared__ float As[16][64];
    __shared__ float Bs[16][64];
    const int m0 = blockIdx.x * 64;
    const int n0 = blockIdx.y * 64;
    const int tid = threadIdx.x;
    const int tr = tid >> 4;    // 0..15
    const int tc = tid & 15;    // 0..15
    float acc[4][4] = {};

    for (int k0 = 0; k0 < K; k0 += 16) {
        #pragma unroll
        for (int p = 0; p < 4; p++) {
            int idx = tid + p * 256;      // 0..1023
            int r   = idx >> 4;           // row 0..63
            int kk  = idx & 15;           // k 0..15
            int gk  = k0 + kk;
            int gm  = m0 + r;
            int gn  = n0 + r;
            As[kk][r] = (gm < M && gk < K) ? A[(size_t)gm * lda + gk] : 0.0f;
            Bs[kk][r] = (gn < N && gk < K) ? Bm[(size_t)gn * ldb + gk] : 0.0f;
        }
        __syncthreads();
        #pragma unroll
        for (int kk = 0; kk < 16; kk++) {
            float af[4], bf[4];
            #pragma unroll
            for (int i = 0; i < 4; i++) { af[i] = As[kk][tr * 4 + i]; bf[i] = Bs[kk][tc * 4 + i]; }
            #pragma unroll
            for (int i = 0; i < 4; i++)
                #pragma unroll
                for (int j = 0; j < 4; j++)
                    acc[i][j] += af[i] * bf[j];
        }
        __syncthreads();
    }
    #pragma unroll
    for (int i = 0; i < 4; i++) {
        int gm = m0 + tr * 4 + i;
        if (gm >= M) continue;
        #pragma unroll
        for (int j = 0; j < 4; j++) {
            int gn = n0 + tc * 4 + j;
            if (gn < N) C[(size_t)gm * ldc + gn] = acc[i][j];
        }
    }
}

// ---------------------------------------------------------------------------
// Fast unguarded SGEMM 128x128x8 (dims must divide). Optional fused epilogue:
//   out = tanh(acc + T1[bs,o] + sum_t a[m,t]*Lab2[l,t,o] + b5[o])
// ---------------------------------------------------------------------------
template <bool EPI>
__global__ __launch_bounds__(256, 2) void sgemm128(
    const float* __restrict__ A, int lda,
    const float* __restrict__ Bm, int ldb,
    float* __restrict__ C, int ldc,
    int K,
    const float* __restrict__ b5)
{
    __shared__ float As[8][128];
    __shared__ float Bs[8][128];
    const int m0 = blockIdx.x * 128;
    const int n0 = blockIdx.y * 128;
    const int tid = threadIdx.x;
    const int lrow = tid >> 1;          // 0..127
    const int lcol = (tid & 1) * 4;     // 0 or 4
    const int ty = tid >> 4;            // 0..15
    const int tx = tid & 15;            // 0..15

    const float* Ag = A + (size_t)(m0 + lrow) * lda + lcol;
    const float* Bg = Bm + (size_t)(n0 + lrow) * ldb + lcol;

    float acc[8][8] = {};

    for (int k0 = 0; k0 < K; k0 += 8) {
        float4 a4 = *(const float4*)(Ag + k0);
        float4 b4 = *(const float4*)(Bg + k0);
        As[lcol + 0][lrow] = a4.x; As[lcol + 1][lrow] = a4.y;
        As[lcol + 2][lrow] = a4.z; As[lcol + 3][lrow] = a4.w;
        Bs[lcol + 0][lrow] = b4.x; Bs[lcol + 1][lrow] = b4.y;
        Bs[lcol + 2][lrow] = b4.z; Bs[lcol + 3][lrow] = b4.w;
        __syncthreads();
        #pragma unroll
        for (int kk = 0; kk < 8; kk++) {
            float4 af0 = *(const float4*)&As[kk][ty * 8];
            float4 af1 = *(const float4*)&As[kk][ty * 8 + 4];
            float4 bf0 = *(const float4*)&Bs[kk][tx * 8];
            float4 bf1 = *(const float4*)&Bs[kk][tx * 8 + 4];
            float af[8] = {af0.x, af0.y, af0.z, af0.w, af1.x, af1.y, af1.z, af1.w};
            float bf[8] = {bf0.x, bf0.y, bf0.z, bf0.w, bf1.x, bf1.y, bf1.z, bf1.w};
            #pragma unroll
            for (int i = 0; i < 8; i++)
                #pragma unroll
                for (int j = 0; j < 8; j++)
                    acc[i][j] += af[i] * bf[j];
        }
        __syncthreads();
    }

    if (!EPI) {
        #pragma unroll
        for (int i = 0; i < 8; i++) {
            float* Cr = C + (size_t)(m0 + ty * 8 + i) * ldc + n0 + tx * 8;
            float4 v0 = make_float4(acc[i][0], acc[i][1], acc[i][2], acc[i][3]);
            float4 v1 = make_float4(acc[i][4], acc[i][5], acc[i][6], acc[i][7]);
            *(float4*)(Cr)     = v0;
            *(float4*)(Cr + 4) = v1;
        }
    } else {
        #pragma unroll
        for (int i = 0; i < 8; i++) {
            int m  = m0 + ty * 8 + i;
            int bs = m / Ln;
            int l  = m - bs * Ln;
            const float* T1r = g_T1 + (size_t)bs * Hn;
            const float* Lr  = g_Lab2 + (size_t)l * LSn * Hn;
            const float* ar  = g_a + (size_t)m * LSn;
            float a0 = ar[0], a1 = ar[1], a2 = ar[2], a3 = ar[3];
            float a4 = ar[4], a5 = ar[5], a6 = ar[6], a7 = ar[7];
            float res[8];
            #pragma unroll
            for (int j = 0; j < 8; j++) {
                int o = n0 + tx * 8 + j;
                float v = acc[i][j] + T1r[o] + b5[o];
                v += a0 * Lr[0 * Hn + o] + a1 * Lr[1 * Hn + o]
                   + a2 * Lr[2 * Hn + o] + a3 * Lr[3 * Hn + o]
                   + a4 * Lr[4 * Hn + o] + a5 * Lr[5 * Hn + o]
                   + a6 * Lr[6 * Hn + o] + a7 * Lr[7 * Hn + o];
                res[j] = tanhf(v);
            }
            float* Cr = C + (size_t)m * ldc + n0 + tx * 8;
            *(float4*)(Cr)     = make_float4(res[0], res[1], res[2], res[3]);
            *(float4*)(Cr + 4) = make_float4(res[4], res[5], res[6], res[7]);
        }
    }
}

// ---------------------------------------------------------------------------
// Softmax over label tokens (t) + b_in = rowmax + input-mask penalty
// One thread per m = (b*S+s)*L + l
// ---------------------------------------------------------------------------
__global__ __launch_bounds__(256) void softmax_a_kernel(
    const float* __restrict__ label_mask,   // [L, LS]
    const float* __restrict__ input_mask)   // [B, S]
{
    int m = blockIdx.x * 256 + threadIdx.x;
    if (m >= MTOT) return;
    int bs = m / Ln;
    int l  = m - bs * Ln;
    float sc[LSn];
    float mx = -INFINITY;
    #pragma unroll
    for (int t = 0; t < LSn; t++) {
        float v = g_scores[(size_t)bs * (Ln * LSn) + l * LSn + t]
                + (1.0f - label_mask[l * LSn + t]) * NEGV;
        sc[t] = v;
        mx = fmaxf(mx, v);
    }
    float sum = 0.0f;
    #pragma unroll
    for (int t = 0; t < LSn; t++) { sc[t] = __expf(sc[t] - mx); sum += sc[t]; }
    float inv = 1.0f / sum;
    #pragma unroll
    for (int t = 0; t < LSn; t++) g_a[(size_t)m * LSn + t] = sc[t] * inv;
    g_bin[m] = mx + (1.0f - input_mask[bs]) * NEGV;
}

// ---------------------------------------------------------------------------
// Softmax over S (context) + q2c[b,l,:] = sum_s w_s * tkn[b,s,:]
// One block per (b,l), 256 threads (== S)
// ---------------------------------------------------------------------------
__global__ __launch_bounds__(256) void q2c_kernel()
{
    int b = blockIdx.x / Ln;
    int l = blockIdx.x - b * Ln;
    int s = threadIdx.x;
    __shared__ float red[256];
    __shared__ float w[256];

    float v = g_bin[(size_t)(b * Sn + s) * Ln + l];
    red[s] = v; __syncthreads();
    for (int off = 128; off > 0; off >>= 1) {
        if (s < off) red[s] = fmaxf(red[s], red[s + off]);
        __syncthreads();
    }
    float mx = red[0]; __syncthreads();
    float e = __expf(v - mx);
    red[s] = e; __syncthreads();
    for (int off = 128; off > 0; off >>= 1) {
        if (s < off) red[s] += red[s + off];
        __syncthreads();
    }
    float inv = 1.0f / red[0];
    w[s] = e * inv;
    __syncthreads();

    for (int h = s; h < Hn; h += 256) {
        float acc = 0.0f;
        #pragma unroll 8
        for (int ss = 0; ss < Sn; ss++)
            acc += w[ss] * g_tkn[(size_t)(b * Sn + ss) * Hn + h];
        g_q2c[(size_t)(b * Ln + l) * Hn + h] = acc;
    }
}

// ---------------------------------------------------------------------------
// Build fused A operand: Af[m, h] = tkn⊙c2q, Af[m, H+h] = tkn⊙q2c
// Block = (l, chunk of 16 bs).  lab[l] + q2c row staged in smem.
// ---------------------------------------------------------------------------
__global__ __launch_bounds__(256) void afused_kernel()
{
    int l   = blockIdx.x;           // 0..19
    int bs0 = blockIdx.y * 16;      // chunk of bs (all share the same b)
    int b   = bs0 / Sn;
    int tid = threadIdx.x;

    __shared__ float labs[LSn * Hn];   // 24 KB
    __shared__ float qv[Hn];           // 3 KB
    __shared__ float av[16][LSn];

    for (int idx = tid; idx < LSn * Hn; idx += 256)
        labs[idx] = g_lab[(size_t)l * LSn * Hn + idx];
    for (int idx = tid; idx < Hn; idx += 256)
        qv[idx] = g_q2c[(size_t)(b * Ln + l) * Hn + idx];
    for (int idx = tid; idx < 16 * LSn; idx += 256) {
        int i = idx >> 3, t = idx & 7;
        av[i][t] = g_a[((size_t)(bs0 + i) * Ln + l) * LSn + t];
    }
    __syncthreads();

    for (int i = 0; i < 16; i++) {
        int bs = bs0 + i;
        size_t m = (size_t)bs * Ln + l;
        float a0 = av[i][0], a1 = av[i][1], a2 = av[i][2], a3 = av[i][3];
        float a4 = av[i][4], a5 = av[i][5], a6 = av[i][6], a7 = av[i][7];
        const float* tr = g_tkn + (size_t)bs * Hn;
        float* Ar = g_Af + m * KF;
        for (int h = tid; h < Hn; h += 256) {
            float c = a0 * labs[h]          + a1 * labs[Hn + h]
                    + a2 * labs[2 * Hn + h] + a3 * labs[3 * Hn + h]
                    + a4 * labs[4 * Hn + h] + a5 * labs[5 * Hn + h]
                    + a6 * labs[6 * Hn + h] + a7 * labs[7 * Hn + h];
            float tv = tr[h];
            Ar[h]      = tv * c;
            Ar[Hn + h] = tv * qv[h];
        }
    }
}

// ---------------------------------------------------------------------------
extern "C" void kernel_launch(void* const* d_in, const int* in_sizes, int n_in,
                              void* d_out, int out_size)
{
    const float* token = (const float*)d_in[0];  // [B,S,H]
    const float* labe  = (const float*)d_in[1];  // [L,LS,E]
    const float* imask = (const float*)d_in[2];  // [B,S]
    const float* lmask = (const float*)d_in[3];  // [L,LS]
    const float* W1    = (const float*)d_in[4];  // [H,H]
    const float* W2    = (const float*)d_in[5];  // [H,E]
    const float* W5    = (const float*)d_in[6];  // [H,4H]
    const float* b5    = (const float*)d_in[7];  // [H]
    float* out = (float*)d_out;                  // [B,S,L,H]

    float *p_tkn, *p_lab, *p_T1, *p_Lab2, *p_scores, *p_Af;
    cudaGetSymbolAddress((void**)&p_tkn,    g_tkn);
    cudaGetSymbolAddress((void**)&p_lab,    g_lab);
    cudaGetSymbolAddress((void**)&p_T1,     g_T1);
    cudaGetSymbolAddress((void**)&p_Lab2,   g_Lab2);
    cudaGetSymbolAddress((void**)&p_scores, g_scores);
    cudaGetSymbolAddress((void**)&p_Af,     g_Af);

    // 1. tkn = token @ W1^T            [2048,768] K=768
    sgemm128<false><<<dim3(BSn / 128, Hn / 128), 256>>>(token, Hn, W1, Hn, p_tkn, Hn, Hn, nullptr);
    // 2. lab = label_embs @ W2^T       [160,768] K=300
    sgemm_abt64<<<dim3(3, 12), 256>>>(labe, En, W2, En, p_lab, Hn, Ln * LSn, Hn, En);
    // 3. T1 = tkn @ W5a^T              [2048,768] K=768
    sgemm128<false><<<dim3(BSn / 128, Hn / 128), 256>>>(p_tkn, Hn, W5, 4 * Hn, p_T1, Hn, Hn, nullptr);
    // 4. Lab2 = lab @ W5b^T            [160,768] K=768
    sgemm_abt64<<<dim3(3, 12), 256>>>(p_lab, Hn, W5 + Hn, 4 * Hn, p_Lab2, Hn, Ln * LSn, Hn, Hn);
    // 5. scores = tkn @ lab^T          [2048,160] K=768
    sgemm_abt64<<<dim3(BSn / 64, 3), 256>>>(p_tkn, Hn, p_lab, Hn, p_scores, Ln * LSn, BSn, Ln * LSn, Hn);
    // 6. softmax over t + b_in
    softmax_a_kernel<<<MTOT / 256, 256>>>(lmask, imask);
    // 7. softmax over s + q2c
    q2c_kernel<<<Bn * Ln, 256>>>();
    // 8. build fused A operand
    afused_kernel<<<dim3(Ln, BSn / 16), 256>>>();
    // 9. fused GEMM + epilogue (T1 + Lab2-term + b5, tanh)
    sgemm128<true><<<dim3(MTOT / 128, Hn / 128), 256>>>(p_Af, KF, W5 + 2 * Hn, 4 * Hn, out, Hn, KF, b5);
}

// round 4
// speedup vs baseline: 1.6668x; 1.6668x over previous
#include <cuda_runtime.h>
#include <math.h>
#include <stdint.h>

// Problem dims
#define Bn   8
#define Sn   256
#define Hn   768
#define Ln   20
#define LSn  8
#define En   300
#define BSn  2048            // B*S
#define MTOT 40960           // B*S*L
#define KF   1536            // fused GEMM K (W5c|W5d)
#define NEGV (-10000.0f)

// ---------------- scratch (static device globals; no allocs allowed) ----------------
__device__ __align__(16) float g_tkn[BSn * Hn];            // 6 MB
__device__ __align__(16) float g_lab[Ln * LSn * Hn];       // 0.5 MB
__device__ __align__(16) float g_T1[BSn * Hn];             // 6 MB   = tkn @ W5a^T
__device__ __align__(16) float g_Lab2[Ln * LSn * Hn];      // 0.5 MB = lab @ W5b^T
__device__ __align__(16) float g_scores[BSn * Ln * LSn];   // 1.3 MB
__device__ __align__(16) float g_a[MTOT * LSn];            // 1.3 MB  softmax probs over t
__device__ __align__(16) float g_bin[MTOT];                // 0.16 MB
__device__ __align__(16) float g_q2c[Bn * Ln * Hn];        // 0.5 MB
__device__ __align__(16) float g_Af[(size_t)MTOT * KF];    // 252 MB  fused A operand

// ---------------------------------------------------------------------------
// Generic guarded SGEMM: C[M,N] = A[M,K] * B[N,K]^T   (64x64x16 tile, 256 thr)
// ---------------------------------------------------------------------------
__global__ __launch_bounds__(256) void sgemm_abt64(
    const float* __restrict__ A, int lda,
    const float* __restrict__ Bm, int ldb,
    float* __restrict__ C, int ldc,
    int M, int N, int K)
{
    __shared__ float As[16][64];
    __shared__ float Bs[16][64];
    const int m0 = blockIdx.x * 64;
    const int n0 = blockIdx.y * 64;
    const int tid = threadIdx.x;
    const int tr = tid >> 4;    // 0..15
    const int tc = tid & 15;    // 0..15
    float acc[4][4] = {};

    for (int k0 = 0; k0 < K; k0 += 16) {
        #pragma unroll
        for (int p = 0; p < 4; p++) {
            int idx = tid + p * 256;      // 0..1023
            int r   = idx >> 4;           // row 0..63
            int kk  = idx & 15;           // k 0..15
            int gk  = k0 + kk;
            int gm  = m0 + r;
            int gn  = n0 + r;
            As[kk][r] = (gm < M && gk < K) ? A[(size_t)gm * lda + gk] : 0.0f;
            Bs[kk][r] = (gn < N && gk < K) ? Bm[(size_t)gn * ldb + gk] : 0.0f;
        }
        __syncthreads();
        #pragma unroll
        for (int kk = 0; kk < 16; kk++) {
            float af[4], bf[4];
            #pragma unroll
            for (int i = 0; i < 4; i++) { af[i] = As[kk][tr * 4 + i]; bf[i] = Bs[kk][tc * 4 + i]; }
            #pragma unroll
            for (int i = 0; i < 4; i++)
                #pragma unroll
                for (int j = 0; j < 4; j++)
                    acc[i][j] += af[i] * bf[j];
        }
        __syncthreads();
    }
    #pragma unroll
    for (int i = 0; i < 4; i++) {
        int gm = m0 + tr * 4 + i;
        if (gm >= M) continue;
        #pragma unroll
        for (int j = 0; j < 4; j++) {
            int gn = n0 + tc * 4 + j;
            if (gn < N) C[(size_t)gm * ldc + gn] = acc[i][j];
        }
    }
}

// ---------------------------------------------------------------------------
// Fast unguarded SGEMM 128x128x8 (dims must divide). Optional fused epilogue:
//   out = tanh(acc + T1[bs,o] + sum_t a[m,t]*Lab2[l,t,o] + b5[o])
// ---------------------------------------------------------------------------
template <bool EPI>
__global__ __launch_bounds__(256, 2) void sgemm128(
    const float* __restrict__ A, int lda,
    const float* __restrict__ Bm, int ldb,
    float* __restrict__ C, int ldc,
    int K,
    const float* __restrict__ b5)
{
    __shared__ float As[8][128];
    __shared__ float Bs[8][128];
    const int m0 = blockIdx.x * 128;
    const int n0 = blockIdx.y * 128;
    const int tid = threadIdx.x;
    const int lrow = tid >> 1;          // 0..127
    const int lcol = (tid & 1) * 4;     // 0 or 4
    const int ty = tid >> 4;            // 0..15
    const int tx = tid & 15;            // 0..15

    const float* Ag = A + (size_t)(m0 + lrow) * lda + lcol;
    const float* Bg = Bm + (size_t)(n0 + lrow) * ldb + lcol;

    float acc[8][8] = {};

    for (int k0 = 0; k0 < K; k0 += 8) {
        float4 a4 = *(const float4*)(Ag + k0);
        float4 b4 = *(const float4*)(Bg + k0);
        As[lcol + 0][lrow] = a4.x; As[lcol + 1][lrow] = a4.y;
        As[lcol + 2][lrow] = a4.z; As[lcol + 3][lrow] = a4.w;
        Bs[lcol + 0][lrow] = b4.x; Bs[lcol + 1][lrow] = b4.y;
        Bs[lcol + 2][lrow] = b4.z; Bs[lcol + 3][lrow] = b4.w;
        __syncthreads();
        #pragma unroll
        for (int kk = 0; kk < 8; kk++) {
            float4 af0 = *(const float4*)&As[kk][ty * 8];
            float4 af1 = *(const float4*)&As[kk][ty * 8 + 4];
            float4 bf0 = *(const float4*)&Bs[kk][tx * 8];
            float4 bf1 = *(const float4*)&Bs[kk][tx * 8 + 4];
            float af[8] = {af0.x, af0.y, af0.z, af0.w, af1.x, af1.y, af1.z, af1.w};
            float bf[8] = {bf0.x, bf0.y, bf0.z, bf0.w, bf1.x, bf1.y, bf1.z, bf1.w};
            #pragma unroll
            for (int i = 0; i < 8; i++)
                #pragma unroll
                for (int j = 0; j < 8; j++)
                    acc[i][j] += af[i] * bf[j];
        }
        __syncthreads();
    }

    if (!EPI) {
        #pragma unroll
        for (int i = 0; i < 8; i++) {
            float* Cr = C + (size_t)(m0 + ty * 8 + i) * ldc + n0 + tx * 8;
            float4 v0 = make_float4(acc[i][0], acc[i][1], acc[i][2], acc[i][3]);
            float4 v1 = make_float4(acc[i][4], acc[i][5], acc[i][6], acc[i][7]);
            *(float4*)(Cr)     = v0;
            *(float4*)(Cr + 4) = v1;
        }
    } else {
        #pragma unroll
        for (int i = 0; i < 8; i++) {
            int m  = m0 + ty * 8 + i;
            int bs = m / Ln;
            int l  = m - bs * Ln;
            const float* T1r = g_T1 + (size_t)bs * Hn;
            const float* Lr  = g_Lab2 + (size_t)l * LSn * Hn;
            const float* ar  = g_a + (size_t)m * LSn;
            float a0 = ar[0], a1 = ar[1], a2 = ar[2], a3 = ar[3];
            float a4 = ar[4], a5 = ar[5], a6 = ar[6], a7 = ar[7];
            float res[8];
            #pragma unroll
            for (int j = 0; j < 8; j++) {
                int o = n0 + tx * 8 + j;
                float v = acc[i][j] + T1r[o] + b5[o];
                v += a0 * Lr[0 * Hn + o] + a1 * Lr[1 * Hn + o]
                   + a2 * Lr[2 * Hn + o] + a3 * Lr[3 * Hn + o]
                   + a4 * Lr[4 * Hn + o] + a5 * Lr[5 * Hn + o]
                   + a6 * Lr[6 * Hn + o] + a7 * Lr[7 * Hn + o];
                res[j] = tanhf(v);
            }
            float* Cr = C + (size_t)m * ldc + n0 + tx * 8;
            *(float4*)(Cr)     = make_float4(res[0], res[1], res[2], res[3]);
            *(float4*)(Cr + 4) = make_float4(res[4], res[5], res[6], res[7]);
        }
    }
}

// ---------------------------------------------------------------------------
// Softmax over label tokens (t) + b_in = rowmax + input-mask penalty
// One thread per m = (b*S+s)*L + l
// ---------------------------------------------------------------------------
__global__ __launch_bounds__(256) void softmax_a_kernel(
    const float* __restrict__ label_mask,   // [L, LS]
    const float* __restrict__ input_mask)   // [B, S]
{
    int m = blockIdx.x * 256 + threadIdx.x;
    if (m >= MTOT) return;
    int bs = m / Ln;
    int l  = m - bs * Ln;
    float sc[LSn];
    float mx = -INFINITY;
    #pragma unroll
    for (int t = 0; t < LSn; t++) {
        float v = g_scores[(size_t)bs * (Ln * LSn) + l * LSn + t]
                + (1.0f - label_mask[l * LSn + t]) * NEGV;
        sc[t] = v;
        mx = fmaxf(mx, v);
    }
    float sum = 0.0f;
    #pragma unroll
    for (int t = 0; t < LSn; t++) { sc[t] = __expf(sc[t] - mx); sum += sc[t]; }
    float inv = 1.0f / sum;
    #pragma unroll
    for (int t = 0; t < LSn; t++) g_a[(size_t)m * LSn + t] = sc[t] * inv;
    g_bin[m] = mx + (1.0f - input_mask[bs]) * NEGV;
}

// ---------------------------------------------------------------------------
// Softmax over S (context) + q2c[b,l,:] = sum_s w_s * tkn[b,s,:]
// One block per (b,l), 256 threads (== S)
// ---------------------------------------------------------------------------
__global__ __launch_bounds__(256) void q2c_kernel()
{
    int b = blockIdx.x / Ln;
    int l = blockIdx.x - b * Ln;
    int s = threadIdx.x;
    __shared__ float red[256];
    __shared__ float w[256];

    float v = g_bin[(size_t)(b * Sn + s) * Ln + l];
    red[s] = v; __syncthreads();
    for (int off = 128; off > 0; off >>= 1) {
        if (s < off) red[s] = fmaxf(red[s], red[s + off]);
        __syncthreads();
    }
    float mx = red[0]; __syncthreads();
    float e = __expf(v - mx);
    red[s] = e; __syncthreads();
    for (int off = 128; off > 0; off >>= 1) {
        if (s < off) red[s] += red[s + off];
        __syncthreads();
    }
    float inv = 1.0f / red[0];
    w[s] = e * inv;
    __syncthreads();

    for (int h = s; h < Hn; h += 256) {
        float acc = 0.0f;
        #pragma unroll 8
        for (int ss = 0; ss < Sn; ss++)
            acc += w[ss] * g_tkn[(size_t)(b * Sn + ss) * Hn + h];
        g_q2c[(size_t)(b * Ln + l) * Hn + h] = acc;
    }
}

// ---------------------------------------------------------------------------
// Build fused A operand: Af[m, h] = tkn⊙c2q, Af[m, H+h] = tkn⊙q2c
// Block = (l, chunk of 16 bs).  lab[l] + q2c row staged in smem.
// ---------------------------------------------------------------------------
__global__ __launch_bounds__(256) void afused_kernel()
{
    int l   = blockIdx.x;           // 0..19
    int bs0 = blockIdx.y * 16;      // chunk of bs (all share the same b)
    int b   = bs0 / Sn;
    int tid = threadIdx.x;

    __shared__ float labs[LSn * Hn];   // 24 KB
    __shared__ float qv[Hn];           // 3 KB
    __shared__ float av[16][LSn];

    for (int idx = tid; idx < LSn * Hn; idx += 256)
        labs[idx] = g_lab[(size_t)l * LSn * Hn + idx];
    for (int idx = tid; idx < Hn; idx += 256)
        qv[idx] = g_q2c[(size_t)(b * Ln + l) * Hn + idx];
    for (int idx = tid; idx < 16 * LSn; idx += 256) {
        int i = idx >> 3, t = idx & 7;
        av[i][t] = g_a[((size_t)(bs0 + i) * Ln + l) * LSn + t];
    }
    __syncthreads();

    for (int i = 0; i < 16; i++) {
        int bs = bs0 + i;
        size_t m = (size_t)bs * Ln + l;
        float a0 = av[i][0], a1 = av[i][1], a2 = av[i][2], a3 = av[i][3];
        float a4 = av[i][4], a5 = av[i][5], a6 = av[i][6], a7 = av[i][7];
        const float* tr = g_tkn + (size_t)bs * Hn;
        float* Ar = g_Af + m * KF;
        for (int h = tid; h < Hn; h += 256) {
            float c = a0 * labs[h]          + a1 * labs[Hn + h]
                    + a2 * labs[2 * Hn + h] + a3 * labs[3 * Hn + h]
                    + a4 * labs[4 * Hn + h] + a5 * labs[5 * Hn + h]
                    + a6 * labs[6 * Hn + h] + a7 * labs[7 * Hn + h];
            float tv = tr[h];
            Ar[h]      = tv * c;
            Ar[Hn + h] = tv * qv[h];
        }
    }
}

// ---------------------------------------------------------------------------
extern "C" void kernel_launch(void* const* d_in, const int* in_sizes, int n_in,
                              void* d_out, int out_size)
{
    const float* token = (const float*)d_in[0];  // [B,S,H]
    const float* labe  = (const float*)d_in[1];  // [L,LS,E]
    const float* imask = (const float*)d_in[2];  // [B,S]
    const float* lmask = (const float*)d_in[3];  // [L,LS]
    const float* W1    = (const float*)d_in[4];  // [H,H]
    const float* W2    = (const float*)d_in[5];  // [H,E]
    const float* W5    = (const float*)d_in[6];  // [H,4H]
    const float* b5    = (const float*)d_in[7];  // [H]
    float* out = (float*)d_out;                  // [B,S,L,H]

    float *p_tkn, *p_lab, *p_T1, *p_Lab2, *p_scores, *p_Af;
    cudaGetSymbolAddress((void**)&p_tkn,    g_tkn);
    cudaGetSymbolAddress((void**)&p_lab,    g_lab);
    cudaGetSymbolAddress((void**)&p_T1,     g_T1);
    cudaGetSymbolAddress((void**)&p_Lab2,   g_Lab2);
    cudaGetSymbolAddress((void**)&p_scores, g_scores);
    cudaGetSymbolAddress((void**)&p_Af,     g_Af);

    // 1. tkn = token @ W1^T            [2048,768] K=768
    sgemm128<false><<<dim3(BSn / 128, Hn / 128), 256>>>(token, Hn, W1, Hn, p_tkn, Hn, Hn, nullptr);
    // 2. lab = label_embs @ W2^T       [160,768] K=300
    sgemm_abt64<<<dim3(3, 12), 256>>>(labe, En, W2, En, p_lab, Hn, Ln * LSn, Hn, En);
    // 3. T1 = tkn @ W5a^T              [2048,768] K=768
    sgemm128<false><<<dim3(BSn / 128, Hn / 128), 256>>>(p_tkn, Hn, W5, 4 * Hn, p_T1, Hn, Hn, nullptr);
    // 4. Lab2 = lab @ W5b^T            [160,768] K=768
    sgemm_abt64<<<dim3(3, 12), 256>>>(p_lab, Hn, W5 + Hn, 4 * Hn, p_Lab2, Hn, Ln * LSn, Hn, Hn);
    // 5. scores = tkn @ lab^T          [2048,160] K=768
    sgemm_abt64<<<dim3(BSn / 64, 3), 256>>>(p_tkn, Hn, p_lab, Hn, p_scores, Ln * LSn, BSn, Ln * LSn, Hn);
    // 6. softmax over t + b_in
    softmax_a_kernel<<<MTOT / 256, 256>>>(lmask, imask);
    // 7. softmax over s + q2c
    q2c_kernel<<<Bn * Ln, 256>>>();
    // 8. build fused A operand
    afused_kernel<<<dim3(Ln, BSn / 16), 256>>>();
    // 9. fused GEMM + epilogue (T1 + Lab2-term + b5, tanh)
    sgemm128<true><<<dim3(MTOT / 128, Hn / 128), 256>>>(p_Af, KF, W5 + 2 * Hn, 4 * Hn, out, Hn, KF, b5);
}

// round 7
// speedup vs baseline: 2.7476x; 1.6485x over previous
#include <cuda_runtime.h>
#include <cuda_bf16.h>
#include <math.h>
#include <stdint.h>

// Problem dims
#define Bn   8
#define Sn   256
#define Hn   768
#define Ln   20
#define LSn  8
#define En   300
#define BSn  2048            // B*S
#define MTOT 40960           // B*S*L
#define NEGV (-10000.0f)

// ---------------- scratch (static device globals; no allocs allowed) ----------------
__device__ __align__(16) float g_tkn[BSn * Hn];
__device__ __align__(16) float g_T1[BSn * Hn];
__device__ __align__(16) float g_lab[Ln * LSn * Hn];
__device__ __align__(16) float g_Lab2[Ln * LSn * Hn];
__device__ __align__(16) float g_scores[BSn * Ln * LSn];
__device__ __align__(16) float g_a[MTOT * LSn];
__device__ __align__(16) float g_bin[MTOT];
__device__ __align__(16) float g_q2c[Bn * Ln * Hn];

__device__ __align__(16) __nv_bfloat16 g_tokhi[BSn * Hn];
__device__ __align__(16) __nv_bfloat16 g_toklo[BSn * Hn];
__device__ __align__(16) __nv_bfloat16 g_tknhi[BSn * Hn];
__device__ __align__(16) __nv_bfloat16 g_tknlo[BSn * Hn];
__device__ __align__(16) __nv_bfloat16 g_W1hi[Hn * Hn];
__device__ __align__(16) __nv_bfloat16 g_W1lo[Hn * Hn];
__device__ __align__(16) __nv_bfloat16 g_W5ahi[Hn * Hn];
__device__ __align__(16) __nv_bfloat16 g_W5alo[Hn * Hn];
__device__ __align__(16) __nv_bfloat16 g_Bhi[Hn * 2 * Hn];      // W5[c|d] as [768,1536]
__device__ __align__(16) __nv_bfloat16 g_Blo[Hn * 2 * Hn];
// Af stored L-MAJOR: row m' = l*2048 + bs
__device__ __align__(16) __nv_bfloat16 g_Afhi[(size_t)MTOT * 1536];   // 126 MB
__device__ __align__(16) __nv_bfloat16 g_Aflo[(size_t)MTOT * 1536];   // 126 MB

__device__ __forceinline__ uint32_t smem_u32(const void* p) {
    uint32_t a;
    asm("{ .reg .u64 t; cvta.to.shared.u64 t, %1; cvt.u32.u64 %0, t; }" : "=r"(a) : "l"(p));
    return a;
}

// SMEM: A stage0 @0, A stage1 @18432, B stage0 @36864, B stage1 @55296
#define ROWPAD 72                 // bf16 elems per row (144 B)
#define STAGEB 18432              // 128*72*2
#define SMEM_SZ 73728

// ---------------------------------------------------------------------------
// bf16-split MMA GEMM: C[M,N] = (Ahi+Alo)[M,K] * (Bhi+Blo)[N,K]^T
// 3 passes over K: Ahi*Bhi, Alo*Bhi, Ahi*Blo. CTA 128x128, K-chunk 64.
// MODE 0: store fp32. MODE 1: fp32 + bf16 hi/lo split to g_tknhi/lo.
// MODE 2: A rows are l-major (m' = l*2048+bs); out[bs*20+l] =
//         tanh(acc + T1[bs] + sum_t a[m,t]*Lab2[l,t] + b5)
// ---------------------------------------------------------------------------
template <int MODE>
__global__ __launch_bounds__(256, 2) void tgemm(
    const __nv_bfloat16* __restrict__ Ahi, const __nv_bfloat16* __restrict__ Alo, int lda,
    const __nv_bfloat16* __restrict__ Bhi, const __nv_bfloat16* __restrict__ Blo, int ldb,
    float* __restrict__ C, int Kd,
    const float* __restrict__ b5)
{
    extern __shared__ char smem[];
    const uint32_t sb = smem_u32(smem);
    const int tid = threadIdx.x;
    const int wid = tid >> 5, lid = tid & 31;
    const int n0 = blockIdx.x * 128, m0 = blockIdx.y * 128;

    const int wm = wid & 1;        // 0..1  -> 64-row slab
    const int wn = wid >> 1;       // 0..3  -> 32-col slab
    const int g  = lid >> 2;       // group id
    const int t4 = lid & 3;        // thread in group

    // ldmatrix per-lane bases
    const int arow = wm * 64 + (lid & 15);
    const int acol = (lid >> 4) * 8;
    const int brow = wn * 32 + (lid & 7);
    const int bcol = ((lid >> 3) & 1) * 8;

    // loader indices: 4 x 16B per thread per matrix per chunk
    const int lrow = tid >> 3;          // with p*32 added below: rows 0..127
    const int lc8  = (tid & 7) * 8;     // elem offset 0..56

    const int NCp = Kd >> 6;
    const int NC  = NCp * 3;

    float acc[4][4][4];
    #pragma unroll
    for (int i = 0; i < 4; i++)
        #pragma unroll
        for (int j = 0; j < 4; j++)
            #pragma unroll
            for (int r = 0; r < 4; r++) acc[i][j][r] = 0.0f;

    auto load_chunk = [&](int c, int s) {
        const int pass = (c >= 2 * NCp) ? 2 : (c >= NCp ? 1 : 0);
        const int k0 = (c - pass * NCp) * 64;
        const __nv_bfloat16* Ap = (pass == 1) ? Alo : Ahi;
        const __nv_bfloat16* Bp = (pass == 2) ? Blo : Bhi;
        const uint32_t aB = sb + s * STAGEB;
        const uint32_t bB = sb + 36864 + s * STAGEB;
        #pragma unroll
        for (int p = 0; p < 4; p++) {
            const int row = lrow + p * 32;
            const uint32_t da = aB + (uint32_t)row * 144 + lc8 * 2;
            const void* ga = Ap + (size_t)(m0 + row) * lda + k0 + lc8;
            asm volatile("cp.async.cg.shared.global [%0], [%1], 16;" :: "r"(da), "l"(ga));
            const uint32_t db = bB + (uint32_t)row * 144 + lc8 * 2;
            const void* gb = Bp + (size_t)(n0 + row) * ldb + k0 + lc8;
            asm volatile("cp.async.cg.shared.global [%0], [%1], 16;" :: "r"(db), "l"(gb));
        }
        asm volatile("cp.async.commit_group;" ::: "memory");
    };

    auto compute = [&](int s) {
        const uint32_t aB = sb + s * STAGEB;
        const uint32_t bB = sb + 36864 + s * STAGEB;
        #pragma unroll
        for (int kk = 0; kk < 4; kk++) {
            uint32_t af[4][4], bf[4][2];
            #pragma unroll
            for (int i = 0; i < 4; i++) {
                const uint32_t ad = aB + (uint32_t)(arow + i * 16) * 144
                                  + (uint32_t)(kk * 16 + acol) * 2;
                asm volatile("ldmatrix.sync.aligned.m8n8.x4.shared.b16 {%0,%1,%2,%3}, [%4];"
                    : "=r"(af[i][0]), "=r"(af[i][1]), "=r"(af[i][2]), "=r"(af[i][3])
                    : "r"(ad));
            }
            #pragma unroll
            for (int j = 0; j < 4; j++) {
                const uint32_t bd = bB + (uint32_t)(brow + j * 8) * 144
                                  + (uint32_t)(kk * 16 + bcol) * 2;
                asm volatile("ldmatrix.sync.aligned.m8n8.x2.shared.b16 {%0,%1}, [%2];"
                    : "=r"(bf[j][0]), "=r"(bf[j][1]) : "r"(bd));
            }
            #pragma unroll
            for (int i = 0; i < 4; i++)
                #pragma unroll
                for (int j = 0; j < 4; j++)
                    asm volatile(
                        "mma.sync.aligned.m16n8k16.row.col.f32.bf16.bf16.f32 "
                        "{%0,%1,%2,%3}, {%4,%5,%6,%7}, {%8,%9}, {%0,%1,%2,%3};"
                        : "+f"(acc[i][j][0]), "+f"(acc[i][j][1]),
                          "+f"(acc[i][j][2]), "+f"(acc[i][j][3])
                        : "r"(af[i][0]), "r"(af[i][1]), "r"(af[i][2]), "r"(af[i][3]),
                          "r"(bf[j][0]), "r"(bf[j][1]));
        }
    };

    load_chunk(0, 0);
    for (int c = 0; c < NC; c++) {
        if (c + 1 < NC) {
            load_chunk(c + 1, (c + 1) & 1);
            asm volatile("cp.async.wait_group 1;" ::: "memory");
        } else {
            asm volatile("cp.async.wait_group 0;" ::: "memory");
        }
        __syncthreads();
        compute(c & 1);
        __syncthreads();
    }

    // ---------------- epilogue ----------------
    if (MODE == 2) {
        const int l   = m0 >> 11;        // 128 | 2048 so each tile is one l
        const int bsb = m0 & 2047;
        float* sLab = (float*)smem;          // [8][128]
        float* sB5  = sLab + 8 * 128;        // [128]
        float* sAv  = sB5 + 128;             // [128][8]
        for (int idx = tid; idx < 1024; idx += 256) {
            const int t = idx >> 7, o = idx & 127;
            sLab[idx] = g_Lab2[(size_t)(l * LSn + t) * Hn + n0 + o];
        }
        if (tid < 128) sB5[tid] = b5[n0 + tid];
        for (int idx = tid; idx < 1024; idx += 256) {
            const int r = idx >> 3, t = idx & 7;
            sAv[idx] = g_a[((size_t)(bsb + r) * Ln + l) * LSn + t];
        }
        __syncthreads();
        #pragma unroll
        for (int i = 0; i < 4; i++) {
            #pragma unroll
            for (int j = 0; j < 4; j++) {
                const int col = wn * 32 + j * 8 + 2 * t4;
                #pragma unroll
                for (int h = 0; h < 2; h++) {
                    const int rl = wm * 64 + i * 16 + g + h * 8;
                    const int bs = bsb + rl;
                    const float2 t1 = *(const float2*)(g_T1 + (size_t)bs * Hn + n0 + col);
                    float v0 = acc[i][j][h * 2]     + t1.x + sB5[col];
                    float v1 = acc[i][j][h * 2 + 1] + t1.y + sB5[col + 1];
                    const float* av = sAv + rl * 8;
                    #pragma unroll
                    for (int t = 0; t < 8; t++) {
                        const float at = av[t];
                        v0 += at * sLab[t * 128 + col];
                        v1 += at * sLab[t * 128 + col + 1];
                    }
                    float2 res = make_float2(tanhf(v0), tanhf(v1));
                    *(float2*)(C + ((size_t)bs * Ln + l) * Hn + n0 + col) = res;
                }
            }
        }
    } else {
        #pragma unroll
        for (int i = 0; i < 4; i++) {
            #pragma unroll
            for (int j = 0; j < 4; j++) {
                const int col = wn * 32 + j * 8 + 2 * t4;
                #pragma unroll
                for (int h = 0; h < 2; h++) {
                    const int m = m0 + wm * 64 + i * 16 + g + h * 8;
                    const float v0 = acc[i][j][h * 2];
                    const float v1 = acc[i][j][h * 2 + 1];
                    *(float2*)(C + (size_t)m * Hn + n0 + col) = make_float2(v0, v1);
                    if (MODE == 1) {
                        const size_t o = (size_t)m * Hn + n0 + col;
                        const __nv_bfloat16 h0 = __float2bfloat16(v0);
                        const __nv_bfloat16 h1 = __float2bfloat16(v1);
                        g_tknhi[o]     = h0;
                        g_tknhi[o + 1] = h1;
                        g_tknlo[o]     = __float2bfloat16(v0 - __bfloat162float(h0));
                        g_tknlo[o + 1] = __float2bfloat16(v1 - __bfloat162float(h1));
                    }
                }
            }
        }
    }
}

// ---------------------------------------------------------------------------
// fp32 -> bf16 hi/lo split (strided source)
// ---------------------------------------------------------------------------
__global__ __launch_bounds__(256) void split_k(
    const float* __restrict__ src, int ld,
    __nv_bfloat16* __restrict__ hi, __nv_bfloat16* __restrict__ lo,
    int Mr, int Kc)
{
    int idx = blockIdx.x * 256 + threadIdx.x;
    if (idx >= Mr * Kc) return;
    int r = idx / Kc, c = idx - r * Kc;
    float x = src[(size_t)r * ld + c];
    __nv_bfloat16 h = __float2bfloat16(x);
    hi[idx] = h;
    lo[idx] = __float2bfloat16(x - __bfloat162float(h));
}

// ---------------------------------------------------------------------------
// Generic guarded SGEMM (small matrices only): C[M,N] = A[M,K] * B[N,K]^T
// ---------------------------------------------------------------------------
__global__ __launch_bounds__(256) void sgemm_abt64(
    const float* __restrict__ A, int lda,
    const float* __restrict__ Bm, int ldb,
    float* __restrict__ C, int ldc,
    int M, int N, int K)
{
    __shared__ float As[16][64];
    __shared__ float Bs[16][64];
    const int m0 = blockIdx.x * 64;
    const int n0 = blockIdx.y * 64;
    const int tid = threadIdx.x;
    const int tr = tid >> 4;
    const int tc = tid & 15;
    float acc[4][4] = {};

    for (int k0 = 0; k0 < K; k0 += 16) {
        #pragma unroll
        for (int p = 0; p < 4; p++) {
            int idx = tid + p * 256;
            int r = idx >> 4;
            int kk = idx & 15;
            int gk = k0 + kk;
            int gm = m0 + r;
            int gn = n0 + r;
            As[kk][r] = (gm < M && gk < K) ? A[(size_t)gm * lda + gk] : 0.0f;
            Bs[kk][r] = (gn < N && gk < K) ? Bm[(size_t)gn * ldb + gk] : 0.0f;
        }
        __syncthreads();
        #pragma unroll
        for (int kk = 0; kk < 16; kk++) {
            float af[4], bf[4];
            #pragma unroll
            for (int i = 0; i < 4; i++) { af[i] = As[kk][tr * 4 + i]; bf[i] = Bs[kk][tc * 4 + i]; }
            #pragma unroll
            for (int i = 0; i < 4; i++)
                #pragma unroll
                for (int j = 0; j < 4; j++)
                    acc[i][j] += af[i] * bf[j];
        }
        __syncthreads();
    }
    #pragma unroll
    for (int i = 0; i < 4; i++) {
        int gm = m0 + tr * 4 + i;
        if (gm >= M) continue;
        #pragma unroll
        for (int j = 0; j < 4; j++) {
            int gn = n0 + tc * 4 + j;
            if (gn < N) C[(size_t)gm * ldc + gn] = acc[i][j];
        }
    }
}

// ---------------------------------------------------------------------------
// Softmax over label tokens + b_in
// ---------------------------------------------------------------------------
__global__ __launch_bounds__(256) void softmax_a_kernel(
    const float* __restrict__ label_mask,
    const float* __restrict__ input_mask)
{
    int m = blockIdx.x * 256 + threadIdx.x;
    if (m >= MTOT) return;
    int bs = m / Ln;
    int l = m - bs * Ln;
    float sc[LSn];
    float mx = -INFINITY;
    #pragma unroll
    for (int t = 0; t < LSn; t++) {
        float v = g_scores[(size_t)bs * (Ln * LSn) + l * LSn + t]
                + (1.0f - label_mask[l * LSn + t]) * NEGV;
        sc[t] = v;
        mx = fmaxf(mx, v);
    }
    float sum = 0.0f;
    #pragma unroll
    for (int t = 0; t < LSn; t++) { sc[t] = __expf(sc[t] - mx); sum += sc[t]; }
    float inv = 1.0f / sum;
    #pragma unroll
    for (int t = 0; t < LSn; t++) g_a[(size_t)m * LSn + t] = sc[t] * inv;
    g_bin[m] = mx + (1.0f - input_mask[bs]) * NEGV;
}

// ---------------------------------------------------------------------------
// Softmax over S + q2c
// ---------------------------------------------------------------------------
__global__ __launch_bounds__(256) void q2c_kernel()
{
    int b = blockIdx.x / Ln;
    int l = blockIdx.x - b * Ln;
    int s = threadIdx.x;
    __shared__ float red[256];
    __shared__ float w[256];

    float v = g_bin[(size_t)(b * Sn + s) * Ln + l];
    red[s] = v; __syncthreads();
    for (int off = 128; off > 0; off >>= 1) {
        if (s < off) red[s] = fmaxf(red[s], red[s + off]);
        __syncthreads();
    }
    float mx = red[0]; __syncthreads();
    float e = __expf(v - mx);
    red[s] = e; __syncthreads();
    for (int off = 128; off > 0; off >>= 1) {
        if (s < off) red[s] += red[s + off];
        __syncthreads();
    }
    float inv = 1.0f / red[0];
    w[s] = e * inv;
    __syncthreads();

    for (int h = s; h < Hn; h += 256) {
        float acc = 0.0f;
        #pragma unroll 8
        for (int ss = 0; ss < Sn; ss++)
            acc += w[ss] * g_tkn[(size_t)(b * Sn + ss) * Hn + h];
        g_q2c[(size_t)(b * Ln + l) * Hn + h] = acc;
    }
}

// ---------------------------------------------------------------------------
// Build fused A operand directly as bf16 hi/lo, L-MAJOR rows (m' = l*2048+bs):
//   Af[m', h]      = tkn*c2q   (h in [0,768))
//   Af[m', 768+h]  = tkn*q2c
// ---------------------------------------------------------------------------
__global__ __launch_bounds__(256) void afused_kernel()
{
    int l   = blockIdx.x;
    int bs0 = blockIdx.y * 16;
    int b   = bs0 / Sn;
    int tid = threadIdx.x;

    __shared__ float labs[LSn * Hn];
    __shared__ float qv[Hn];
    __shared__ float av[16][LSn];

    for (int idx = tid; idx < LSn * Hn; idx += 256)
        labs[idx] = g_lab[(size_t)l * LSn * Hn + idx];
    for (int idx = tid; idx < Hn; idx += 256)
        qv[idx] = g_q2c[(size_t)(b * Ln + l) * Hn + idx];
    for (int idx = tid; idx < 16 * LSn; idx += 256) {
        int i = idx >> 3, t = idx & 7;
        av[i][t] = g_a[((size_t)(bs0 + i) * Ln + l) * LSn + t];
    }
    __syncthreads();

    for (int i = 0; i < 16; i++) {
        int bs = bs0 + i;
        size_t m = (size_t)l * BSn + bs;     // l-major row
        float a0 = av[i][0], a1 = av[i][1], a2 = av[i][2], a3 = av[i][3];
        float a4 = av[i][4], a5 = av[i][5], a6 = av[i][6], a7 = av[i][7];
        const float* tr = g_tkn + (size_t)bs * Hn;
        __nv_bfloat16* Ah = g_Afhi + m * 1536;
        __nv_bfloat16* Al = g_Aflo + m * 1536;
        for (int h = tid; h < Hn; h += 256) {
            float c = a0 * labs[h]          + a1 * labs[Hn + h]
                    + a2 * labs[2 * Hn + h] + a3 * labs[3 * Hn + h]
                    + a4 * labs[4 * Hn + h] + a5 * labs[5 * Hn + h]
                    + a6 * labs[6 * Hn + h] + a7 * labs[7 * Hn + h];
            float tv = tr[h];
            float v1 = tv * c;
            float v2 = tv * qv[h];
            __nv_bfloat16 h1 = __float2bfloat16(v1);
            Ah[h] = h1;
            Al[h] = __float2bfloat16(v1 - __bfloat162float(h1));
            __nv_bfloat16 h2 = __float2bfloat16(v2);
            Ah[Hn + h] = h2;
            Al[Hn + h] = __float2bfloat16(v2 - __bfloat162float(h2));
        }
    }
}

// ---------------------------------------------------------------------------
extern "C" void kernel_launch(void* const* d_in, const int* in_sizes, int n_in,
                              void* d_out, int out_size)
{
    const float* token = (const float*)d_in[0];
    const float* labe  = (const float*)d_in[1];
    const float* imask = (const float*)d_in[2];
    const float* lmask = (const float*)d_in[3];
    const float* W1    = (const float*)d_in[4];
    const float* W2    = (const float*)d_in[5];
    const float* W5    = (const float*)d_in[6];
    const float* b5    = (const float*)d_in[7];
    float* out = (float*)d_out;

    float *p_tkn, *p_lab, *p_T1, *p_Lab2, *p_scores;
    __nv_bfloat16 *p_tokhi, *p_toklo, *p_tknhi, *p_tknlo;
    __nv_bfloat16 *p_W1hi, *p_W1lo, *p_W5ahi, *p_W5alo, *p_Bhi, *p_Blo, *p_Afhi, *p_Aflo;
    cudaGetSymbolAddress((void**)&p_tkn,    g_tkn);
    cudaGetSymbolAddress((void**)&p_lab,    g_lab);
    cudaGetSymbolAddress((void**)&p_T1,     g_T1);
    cudaGetSymbolAddress((void**)&p_Lab2,   g_Lab2);
    cudaGetSymbolAddress((void**)&p_scores, g_scores);
    cudaGetSymbolAddress((void**)&p_tokhi,  g_tokhi);
    cudaGetSymbolAddress((void**)&p_toklo,  g_toklo);
    cudaGetSymbolAddress((void**)&p_tknhi,  g_tknhi);
    cudaGetSymbolAddress((void**)&p_tknlo,  g_tknlo);
    cudaGetSymbolAddress((void**)&p_W1hi,   g_W1hi);
    cudaGetSymbolAddress((void**)&p_W1lo,   g_W1lo);
    cudaGetSymbolAddress((void**)&p_W5ahi,  g_W5ahi);
    cudaGetSymbolAddress((void**)&p_W5alo,  g_W5alo);
    cudaGetSymbolAddress((void**)&p_Bhi,    g_Bhi);
    cudaGetSymbolAddress((void**)&p_Blo,    g_Blo);
    cudaGetSymbolAddress((void**)&p_Afhi,   g_Afhi);
    cudaGetSymbolAddress((void**)&p_Aflo,   g_Aflo);

    cudaFuncSetAttribute(tgemm<0>, cudaFuncAttributeMaxDynamicSharedMemorySize, SMEM_SZ);
    cudaFuncSetAttribute(tgemm<1>, cudaFuncAttributeMaxDynamicSharedMemorySize, SMEM_SZ);
    cudaFuncSetAttribute(tgemm<2>, cudaFuncAttributeMaxDynamicSharedMemorySize, SMEM_SZ);

    // splits
    split_k<<<(BSn * Hn + 255) / 256, 256>>>(token, Hn, p_tokhi, p_toklo, BSn, Hn);
    split_k<<<(Hn * Hn + 255) / 256, 256>>>(W1, Hn, p_W1hi, p_W1lo, Hn, Hn);
    split_k<<<(Hn * Hn + 255) / 256, 256>>>(W5, 4 * Hn, p_W5ahi, p_W5alo, Hn, Hn);
    split_k<<<(Hn * 2 * Hn + 255) / 256, 256>>>(W5 + 2 * Hn, 4 * Hn, p_Bhi, p_Blo, Hn, 2 * Hn);

    // lab = label_embs @ W2^T   [160,768] K=300 (fp32, tiny)
    sgemm_abt64<<<dim3(3, 12), 256>>>(labe, En, W2, En, p_lab, Hn, Ln * LSn, Hn, En);
    // tkn = token @ W1^T (tensor HMMA, fp32 out + hi/lo split)
    tgemm<1><<<dim3(6, 16), 256, SMEM_SZ>>>(p_tokhi, p_toklo, Hn, p_W1hi, p_W1lo, Hn,
                                            p_tkn, Hn, nullptr);
    // T1 = tkn @ W5a^T (tensor)
    tgemm<0><<<dim3(6, 16), 256, SMEM_SZ>>>(p_tknhi, p_tknlo, Hn, p_W5ahi, p_W5alo, Hn,
                                            p_T1, Hn, nullptr);
    // Lab2 = lab @ W5b^T   [160,768] K=768 (fp32)
    sgemm_abt64<<<dim3(3, 12), 256>>>(p_lab, Hn, W5 + Hn, 4 * Hn, p_Lab2, Hn, Ln * LSn, Hn, Hn);
    // scores = tkn @ lab^T [2048,160] K=768 (fp32)
    sgemm_abt64<<<dim3(BSn / 64, 3), 256>>>(p_tkn, Hn, p_lab, Hn, p_scores, Ln * LSn,
                                            BSn, Ln * LSn, Hn);
    // softmaxes
    softmax_a_kernel<<<MTOT / 256, 256>>>(lmask, imask);
    q2c_kernel<<<Bn * Ln, 256>>>();
    // fused A operand (bf16 hi/lo, l-major)
    afused_kernel<<<dim3(Ln, BSn / 16), 256>>>();
    // big fused GEMM + epilogue (tensor)
    tgemm<2><<<dim3(6, 320), 256, SMEM_SZ>>>(p_Afhi, p_Aflo, 2 * Hn, p_Bhi, p_Blo, 2 * Hn,
                                             out, 2 * Hn, b5);
}

// round 8
// speedup vs baseline: 5.7382x; 2.0884x over previous
#include <cuda_runtime.h>
#include <cuda_fp16.h>
#include <math.h>
#include <stdint.h>

// Problem dims
#define Bn   8
#define Sn   256
#define Hn   768
#define Ln   20
#define LSn  8
#define En   300
#define BSn  2048            // B*S
#define MTOT 40960           // B*S*L
#define NEGV (-10000.0f)

// ---------------- scratch (static device globals; no allocs allowed) ----------------
__device__ __align__(16) float g_tkn[BSn * Hn];
__device__ __align__(16) float g_T1[BSn * Hn];
__device__ __align__(16) float g_lab[Ln * LSn * Hn];
__device__ __align__(16) float g_Lab2[Ln * LSn * Hn];
__device__ __align__(16) float g_scores[BSn * Ln * LSn];
__device__ __align__(16) float g_a[MTOT * LSn];
__device__ __align__(16) float g_bin[MTOT];
__device__ __align__(16) float g_q2c[Bn * Ln * Hn];

__device__ __align__(16) __half g_tokhi[BSn * Hn];
__device__ __align__(16) __half g_toklo[BSn * Hn];
__device__ __align__(16) __half g_tknhi[BSn * Hn];
__device__ __align__(16) __half g_tknlo[BSn * Hn];
__device__ __align__(16) __half g_W1hi[Hn * Hn];
__device__ __align__(16) __half g_W1lo[Hn * Hn];
__device__ __align__(16) __half g_W5ahi[Hn * Hn];
__device__ __align__(16) __half g_W5alo[Hn * Hn];
__device__ __align__(16) __half g_Bhi[Hn * 2 * Hn];      // W5[c|d] as [768,1536]
__device__ __align__(16) __half g_Blo[Hn * 2 * Hn];      // produced; unused by 2-pass GEMM
// Af stored L-MAJOR: row m' = l*2048 + bs
__device__ __align__(16) __half g_Afhi[(size_t)MTOT * 1536];   // 126 MB
__device__ __align__(16) __half g_Aflo[(size_t)MTOT * 1536];   // 126 MB

__device__ __forceinline__ uint32_t smem_u32(const void* p) {
    uint32_t a;
    asm("{ .reg .u64 t; cvta.to.shared.u64 t, %1; cvt.u32.u64 %0, t; }" : "=r"(a) : "l"(p));
    return a;
}

// fp16 hi/lo split of a float4 -> two packed 8B values
__device__ __forceinline__ void split4(float4 v, uint2& hi, uint2& lo) {
    __half h0 = __float2half_rn(v.x), h1 = __float2half_rn(v.y);
    __half h2 = __float2half_rn(v.z), h3 = __float2half_rn(v.w);
    __half l0 = __float2half_rn(v.x - __half2float(h0));
    __half l1 = __float2half_rn(v.y - __half2float(h1));
    __half l2 = __float2half_rn(v.z - __half2float(h2));
    __half l3 = __float2half_rn(v.w - __half2float(h3));
    __half2 ph0 = __halves2half2(h0, h1), ph1 = __halves2half2(h2, h3);
    __half2 pl0 = __halves2half2(l0, l1), pl1 = __halves2half2(l2, l3);
    hi.x = *reinterpret_cast<uint32_t*>(&ph0);
    hi.y = *reinterpret_cast<uint32_t*>(&ph1);
    lo.x = *reinterpret_cast<uint32_t*>(&pl0);
    lo.y = *reinterpret_cast<uint32_t*>(&pl1);
}

// SMEM: A stage0 @0, A stage1 @18432, B stage0 @36864, B stage1 @55296
#define STAGEB 18432              // 128*72*2 bytes (row padded to 144B)
#define SMEM_SZ 73728

// ---------------------------------------------------------------------------
// fp16-split MMA GEMM: C[M,N] = A[M,K] * B[N,K]^T
// PASS=3: Ahi*Bhi + Alo*Bhi + Ahi*Blo (error ~2^-22)
// PASS=2: Ahi*Bhi + Alo*Bhi           (error ~2^-12 statistical)
// MODE 0: store fp32. MODE 1: fp32 + fp16 hi/lo split to g_tknhi/lo.
// MODE 2: A rows are l-major (m' = l*2048+bs); out[bs*20+l] =
//         tanh(acc + T1[bs] + sum_t a[m,t]*Lab2[l,t] + b5)
// ---------------------------------------------------------------------------
template <int MODE, int PASS>
__global__ __launch_bounds__(256, 2) void tgemm(
    const __half* __restrict__ Ahi, const __half* __restrict__ Alo, int lda,
    const __half* __restrict__ Bhi, const __half* __restrict__ Blo, int ldb,
    float* __restrict__ C, int Kd,
    const float* __restrict__ b5)
{
    extern __shared__ char smem[];
    const uint32_t sb = smem_u32(smem);
    const int tid = threadIdx.x;
    const int wid = tid >> 5, lid = tid & 31;
    const int n0 = blockIdx.x * 128, m0 = blockIdx.y * 128;

    const int wm = wid & 1;        // 0..1  -> 64-row slab
    const int wn = wid >> 1;       // 0..3  -> 32-col slab
    const int g  = lid >> 2;       // group id
    const int t4 = lid & 3;        // thread in group

    const int arow = wm * 64 + (lid & 15);
    const int acol = (lid >> 4) * 8;
    const int brow = wn * 32 + (lid & 7);
    const int bcol = ((lid >> 3) & 1) * 8;

    const int lrow = tid >> 3;
    const int lc8  = (tid & 7) * 8;

    const int NCp = Kd >> 6;
    const int NC  = NCp * PASS;

    float acc[4][4][4];
    #pragma unroll
    for (int i = 0; i < 4; i++)
        #pragma unroll
        for (int j = 0; j < 4; j++)
            #pragma unroll
            for (int r = 0; r < 4; r++) acc[i][j][r] = 0.0f;

    auto load_chunk = [&](int c, int s) {
        const int pass = (c >= 2 * NCp) ? 2 : (c >= NCp ? 1 : 0);
        const int k0 = (c - pass * NCp) * 64;
        const __half* Ap = (pass == 1) ? Alo : Ahi;
        const __half* Bp = (pass == 2) ? Blo : Bhi;
        const uint32_t aB = sb + s * STAGEB;
        const uint32_t bB = sb + 36864 + s * STAGEB;
        #pragma unroll
        for (int p = 0; p < 4; p++) {
            const int row = lrow + p * 32;
            const uint32_t da = aB + (uint32_t)row * 144 + lc8 * 2;
            const void* ga = Ap + (size_t)(m0 + row) * lda + k0 + lc8;
            asm volatile("cp.async.cg.shared.global [%0], [%1], 16;" :: "r"(da), "l"(ga));
            const uint32_t db = bB + (uint32_t)row * 144 + lc8 * 2;
            const void* gb = Bp + (size_t)(n0 + row) * ldb + k0 + lc8;
            asm volatile("cp.async.cg.shared.global [%0], [%1], 16;" :: "r"(db), "l"(gb));
        }
        asm volatile("cp.async.commit_group;" ::: "memory");
    };

    auto compute = [&](int s) {
        const uint32_t aB = sb + s * STAGEB;
        const uint32_t bB = sb + 36864 + s * STAGEB;
        #pragma unroll
        for (int kk = 0; kk < 4; kk++) {
            uint32_t af[4][4], bf[4][2];
            #pragma unroll
            for (int i = 0; i < 4; i++) {
                const uint32_t ad = aB + (uint32_t)(arow + i * 16) * 144
                                  + (uint32_t)(kk * 16 + acol) * 2;
                asm volatile("ldmatrix.sync.aligned.m8n8.x4.shared.b16 {%0,%1,%2,%3}, [%4];"
                    : "=r"(af[i][0]), "=r"(af[i][1]), "=r"(af[i][2]), "=r"(af[i][3])
                    : "r"(ad));
            }
            #pragma unroll
            for (int j = 0; j < 4; j++) {
                const uint32_t bd = bB + (uint32_t)(brow + j * 8) * 144
                                  + (uint32_t)(kk * 16 + bcol) * 2;
                asm volatile("ldmatrix.sync.aligned.m8n8.x2.shared.b16 {%0,%1}, [%2];"
                    : "=r"(bf[j][0]), "=r"(bf[j][1]) : "r"(bd));
            }
            #pragma unroll
            for (int i = 0; i < 4; i++)
                #pragma unroll
                for (int j = 0; j < 4; j++)
                    asm volatile(
                        "mma.sync.aligned.m16n8k16.row.col.f32.f16.f16.f32 "
                        "{%0,%1,%2,%3}, {%4,%5,%6,%7}, {%8,%9}, {%0,%1,%2,%3};"
                        : "+f"(acc[i][j][0]), "+f"(acc[i][j][1]),
                          "+f"(acc[i][j][2]), "+f"(acc[i][j][3])
                        : "r"(af[i][0]), "r"(af[i][1]), "r"(af[i][2]), "r"(af[i][3]),
                          "r"(bf[j][0]), "r"(bf[j][1]));
        }
    };

    load_chunk(0, 0);
    for (int c = 0; c < NC; c++) {
        if (c + 1 < NC) {
            load_chunk(c + 1, (c + 1) & 1);
            asm volatile("cp.async.wait_group 1;" ::: "memory");
        } else {
            asm volatile("cp.async.wait_group 0;" ::: "memory");
        }
        __syncthreads();
        compute(c & 1);
        __syncthreads();
    }

    // ---------------- epilogue ----------------
    if (MODE == 2) {
        const int l   = m0 >> 11;        // 128 | 2048 so each tile is one l
        const int bsb = m0 & 2047;
        float* sLab = (float*)smem;          // [8][128]
        float* sB5  = sLab + 8 * 128;        // [128]
        float* sAv  = sB5 + 128;             // [128][8]
        for (int idx = tid; idx < 1024; idx += 256) {
            const int t = idx >> 7, o = idx & 127;
            sLab[idx] = g_Lab2[(size_t)(l * LSn + t) * Hn + n0 + o];
        }
        if (tid < 128) sB5[tid] = b5[n0 + tid];
        for (int idx = tid; idx < 1024; idx += 256) {
            const int r = idx >> 3, t = idx & 7;
            sAv[idx] = g_a[((size_t)(bsb + r) * Ln + l) * LSn + t];
        }
        __syncthreads();
        #pragma unroll
        for (int i = 0; i < 4; i++) {
            #pragma unroll
            for (int j = 0; j < 4; j++) {
                const int col = wn * 32 + j * 8 + 2 * t4;
                #pragma unroll
                for (int h = 0; h < 2; h++) {
                    const int rl = wm * 64 + i * 16 + g + h * 8;
                    const int bs = bsb + rl;
                    const float2 t1 = *(const float2*)(g_T1 + (size_t)bs * Hn + n0 + col);
                    float v0 = acc[i][j][h * 2]     + t1.x + sB5[col];
                    float v1 = acc[i][j][h * 2 + 1] + t1.y + sB5[col + 1];
                    const float* av = sAv + rl * 8;
                    #pragma unroll
                    for (int t = 0; t < 8; t++) {
                        const float at = av[t];
                        v0 += at * sLab[t * 128 + col];
                        v1 += at * sLab[t * 128 + col + 1];
                    }
                    float2 res = make_float2(tanhf(v0), tanhf(v1));
                    *(float2*)(C + ((size_t)bs * Ln + l) * Hn + n0 + col) = res;
                }
            }
        }
    } else {
        #pragma unroll
        for (int i = 0; i < 4; i++) {
            #pragma unroll
            for (int j = 0; j < 4; j++) {
                const int col = wn * 32 + j * 8 + 2 * t4;
                #pragma unroll
                for (int h = 0; h < 2; h++) {
                    const int m = m0 + wm * 64 + i * 16 + g + h * 8;
                    const float v0 = acc[i][j][h * 2];
                    const float v1 = acc[i][j][h * 2 + 1];
                    *(float2*)(C + (size_t)m * Hn + n0 + col) = make_float2(v0, v1);
                    if (MODE == 1) {
                        const size_t o = (size_t)m * Hn + n0 + col;
                        __half h0 = __float2half_rn(v0);
                        __half h1 = __float2half_rn(v1);
                        __half l0 = __float2half_rn(v0 - __half2float(h0));
                        __half l1 = __float2half_rn(v1 - __half2float(h1));
                        *(__half2*)(g_tknhi + o) = __halves2half2(h0, h1);
                        *(__half2*)(g_tknlo + o) = __halves2half2(l0, l1);
                    }
                }
            }
        }
    }
}

// ---------------------------------------------------------------------------
// fp32 -> fp16 hi/lo split (strided source)
// ---------------------------------------------------------------------------
__global__ __launch_bounds__(256) void split_k(
    const float* __restrict__ src, int ld,
    __half* __restrict__ hi, __half* __restrict__ lo,
    int Mr, int Kc)
{
    int idx = blockIdx.x * 256 + threadIdx.x;
    if (idx >= Mr * Kc) return;
    int r = idx / Kc, c = idx - r * Kc;
    float x = src[(size_t)r * ld + c];
    __half h = __float2half_rn(x);
    hi[idx] = h;
    lo[idx] = __float2half_rn(x - __half2float(h));
}

// ---------------------------------------------------------------------------
// Small guarded SGEMM, 32x32 tile (high CTA count): C[M,N] = A[M,K]*B[N,K]^T
// ---------------------------------------------------------------------------
__global__ __launch_bounds__(256) void sgemm32(
    const float* __restrict__ A, int lda,
    const float* __restrict__ Bm, int ldb,
    float* __restrict__ C, int ldc,
    int M, int N, int K)
{
    __shared__ float As[32][33];
    __shared__ float Bs[32][33];
    const int m0 = blockIdx.x * 32;
    const int n0 = blockIdx.y * 32;
    const int tid = threadIdx.x;
    const int tr = tid >> 4;     // 0..15
    const int tc = tid & 15;     // 0..15
    float acc[2][2] = {};

    for (int k0 = 0; k0 < K; k0 += 32) {
        #pragma unroll
        for (int p = 0; p < 4; p++) {
            int idx = tid + p * 256;
            int r = idx >> 5;
            int kk = idx & 31;
            int gk = k0 + kk;
            int gm = m0 + r;
            int gn = n0 + r;
            As[kk][r] = (gm < M && gk < K) ? A[(size_t)gm * lda + gk] : 0.0f;
            Bs[kk][r] = (gn < N && gk < K) ? Bm[(size_t)gn * ldb + gk] : 0.0f;
        }
        __syncthreads();
        #pragma unroll
        for (int kk = 0; kk < 32; kk++) {
            float a0 = As[kk][tr * 2], a1 = As[kk][tr * 2 + 1];
            float b0 = Bs[kk][tc * 2], b1 = Bs[kk][tc * 2 + 1];
            acc[0][0] += a0 * b0; acc[0][1] += a0 * b1;
            acc[1][0] += a1 * b0; acc[1][1] += a1 * b1;
        }
        __syncthreads();
    }
    #pragma unroll
    for (int i = 0; i < 2; i++) {
        int gm = m0 + tr * 2 + i;
        if (gm >= M) continue;
        #pragma unroll
        for (int j = 0; j < 2; j++) {
            int gn = n0 + tc * 2 + j;
            if (gn < N) C[(size_t)gm * ldc + gn] = acc[i][j];
        }
    }
}

// ---------------------------------------------------------------------------
// Softmax over label tokens + b_in
// ---------------------------------------------------------------------------
__global__ __launch_bounds__(256) void softmax_a_kernel(
    const float* __restrict__ label_mask,
    const float* __restrict__ input_mask)
{
    int m = blockIdx.x * 256 + threadIdx.x;
    if (m >= MTOT) return;
    int bs = m / Ln;
    int l = m - bs * Ln;
    float sc[LSn];
    float mx = -INFINITY;
    #pragma unroll
    for (int t = 0; t < LSn; t++) {
        float v = g_scores[(size_t)bs * (Ln * LSn) + l * LSn + t]
                + (1.0f - label_mask[l * LSn + t]) * NEGV;
        sc[t] = v;
        mx = fmaxf(mx, v);
    }
    float sum = 0.0f;
    #pragma unroll
    for (int t = 0; t < LSn; t++) { sc[t] = __expf(sc[t] - mx); sum += sc[t]; }
    float inv = 1.0f / sum;
    #pragma unroll
    for (int t = 0; t < LSn; t++) g_a[(size_t)m * LSn + t] = sc[t] * inv;
    g_bin[m] = mx + (1.0f - input_mask[bs]) * NEGV;
}

// ---------------------------------------------------------------------------
// Softmax over S + q2c
// ---------------------------------------------------------------------------
__global__ __launch_bounds__(256) void q2c_kernel()
{
    int b = blockIdx.x / Ln;
    int l = blockIdx.x - b * Ln;
    int s = threadIdx.x;
    __shared__ float red[256];
    __shared__ float w[256];

    float v = g_bin[(size_t)(b * Sn + s) * Ln + l];
    red[s] = v; __syncthreads();
    for (int off = 128; off > 0; off >>= 1) {
        if (s < off) red[s] = fmaxf(red[s], red[s + off]);
        __syncthreads();
    }
    float mx = red[0]; __syncthreads();
    float e = __expf(v - mx);
    red[s] = e; __syncthreads();
    for (int off = 128; off > 0; off >>= 1) {
        if (s < off) red[s] += red[s + off];
        __syncthreads();
    }
    float inv = 1.0f / red[0];
    w[s] = e * inv;
    __syncthreads();

    for (int h = s; h < Hn; h += 256) {
        float acc = 0.0f;
        #pragma unroll 8
        for (int ss = 0; ss < Sn; ss++)
            acc += w[ss] * g_tkn[(size_t)(b * Sn + ss) * Hn + h];
        g_q2c[(size_t)(b * Ln + l) * Hn + h] = acc;
    }
}

// ---------------------------------------------------------------------------
// Build fused A operand as fp16 hi/lo, L-MAJOR rows (m' = l*2048+bs):
//   Af[m', h]      = tkn*c2q   (h in [0,768))
//   Af[m', 768+h]  = tkn*q2c
// Vectorized: float4 reads, 8B packed half stores.
// ---------------------------------------------------------------------------
__global__ __launch_bounds__(256) void afused_kernel()
{
    int l   = blockIdx.x;
    int bs0 = blockIdx.y * 16;
    int b   = bs0 / Sn;
    int tid = threadIdx.x;

    __shared__ float labs[LSn * Hn];
    __shared__ float qv[Hn];
    __shared__ float av[16][LSn];

    for (int idx = tid; idx < LSn * Hn; idx += 256)
        labs[idx] = g_lab[(size_t)l * LSn * Hn + idx];
    for (int idx = tid; idx < Hn; idx += 256)
        qv[idx] = g_q2c[(size_t)(b * Ln + l) * Hn + idx];
    for (int idx = tid; idx < 16 * LSn; idx += 256) {
        int i = idx >> 3, t = idx & 7;
        av[i][t] = g_a[((size_t)(bs0 + i) * Ln + l) * LSn + t];
    }
    __syncthreads();

    const int hc = tid * 4;          // threads 0..191 active (192*4 = 768)
    for (int i = 0; i < 16; i++) {
        int bs = bs0 + i;
        size_t m = (size_t)l * BSn + bs;     // l-major row
        if (hc < Hn) {
            float a0 = av[i][0], a1 = av[i][1], a2 = av[i][2], a3 = av[i][3];
            float a4 = av[i][4], a5 = av[i][5], a6 = av[i][6], a7 = av[i][7];
            const float4 tv = *(const float4*)(g_tkn + (size_t)bs * Hn + hc);
            const float4 qv4 = *(const float4*)(qv + hc);
            float4 c = make_float4(0.f, 0.f, 0.f, 0.f);
            #pragma unroll
            for (int t = 0; t < LSn; t++) {
                const float at = (t == 0) ? a0 : (t == 1) ? a1 : (t == 2) ? a2 :
                                 (t == 3) ? a3 : (t == 4) ? a4 : (t == 5) ? a5 :
                                 (t == 6) ? a6 : a7;
                const float4 lb = *(const float4*)(labs + t * Hn + hc);
                c.x += at * lb.x; c.y += at * lb.y;
                c.z += at * lb.z; c.w += at * lb.w;
            }
            float4 v1 = make_float4(tv.x * c.x, tv.y * c.y, tv.z * c.z, tv.w * c.w);
            float4 v2 = make_float4(tv.x * qv4.x, tv.y * qv4.y, tv.z * qv4.z, tv.w * qv4.w);
            uint2 h1, l1, h2, l2;
            split4(v1, h1, l1);
            split4(v2, h2, l2);
            __half* Ah = g_Afhi + m * 1536;
            __half* Al = g_Aflo + m * 1536;
            *(uint2*)(Ah + hc)      = h1;
            *(uint2*)(Al + hc)      = l1;
            *(uint2*)(Ah + Hn + hc) = h2;
            *(uint2*)(Al + Hn + hc) = l2;
        }
    }
}

// ---------------------------------------------------------------------------
extern "C" void kernel_launch(void* const* d_in, const int* in_sizes, int n_in,
                              void* d_out, int out_size)
{
    const float* token = (const float*)d_in[0];
    const float* labe  = (const float*)d_in[1];
    const float* imask = (const float*)d_in[2];
    const float* lmask = (const float*)d_in[3];
    const float* W1    = (const float*)d_in[4];
    const float* W2    = (const float*)d_in[5];
    const float* W5    = (const float*)d_in[6];
    const float* b5    = (const float*)d_in[7];
    float* out = (float*)d_out;

    float *p_tkn, *p_lab, *p_T1, *p_Lab2, *p_scores;
    __half *p_tokhi, *p_toklo, *p_tknhi, *p_tknlo;
    __half *p_W1hi, *p_W1lo, *p_W5ahi, *p_W5alo, *p_Bhi, *p_Blo, *p_Afhi, *p_Aflo;
    cudaGetSymbolAddress((void**)&p_tkn,    g_tkn);
    cudaGetSymbolAddress((void**)&p_lab,    g_lab);
    cudaGetSymbolAddress((void**)&p_T1,     g_T1);
    cudaGetSymbolAddress((void**)&p_Lab2,   g_Lab2);
    cudaGetSymbolAddress((void**)&p_scores, g_scores);
    cudaGetSymbolAddress((void**)&p_tokhi,  g_tokhi);
    cudaGetSymbolAddress((void**)&p_toklo,  g_toklo);
    cudaGetSymbolAddress((void**)&p_tknhi,  g_tknhi);
    cudaGetSymbolAddress((void**)&p_tknlo,  g_tknlo);
    cudaGetSymbolAddress((void**)&p_W1hi,   g_W1hi);
    cudaGetSymbolAddress((void**)&p_W1lo,   g_W1lo);
    cudaGetSymbolAddress((void**)&p_W5ahi,  g_W5ahi);
    cudaGetSymbolAddress((void**)&p_W5alo,  g_W5alo);
    cudaGetSymbolAddress((void**)&p_Bhi,    g_Bhi);
    cudaGetSymbolAddress((void**)&p_Blo,    g_Blo);
    cudaGetSymbolAddress((void**)&p_Afhi,   g_Afhi);
    cudaGetSymbolAddress((void**)&p_Aflo,   g_Aflo);

    cudaFuncSetAttribute((const void*)tgemm<0,3>, cudaFuncAttributeMaxDynamicSharedMemorySize, SMEM_SZ);
    cudaFuncSetAttribute((const void*)tgemm<1,3>, cudaFuncAttributeMaxDynamicSharedMemorySize, SMEM_SZ);
    cudaFuncSetAttribute((const void*)tgemm<2,2>, cudaFuncAttributeMaxDynamicSharedMemorySize, SMEM_SZ);

    // splits (fp16 hi/lo)
    split_k<<<(BSn * Hn + 255) / 256, 256>>>(token, Hn, p_tokhi, p_toklo, BSn, Hn);
    split_k<<<(Hn * Hn + 255) / 256, 256>>>(W1, Hn, p_W1hi, p_W1lo, Hn, Hn);
    split_k<<<(Hn * Hn + 255) / 256, 256>>>(W5, 4 * Hn, p_W5ahi, p_W5alo, Hn, Hn);
    split_k<<<(Hn * 2 * Hn + 255) / 256, 256>>>(W5 + 2 * Hn, 4 * Hn, p_Bhi, p_Blo, Hn, 2 * Hn);

    // lab = label_embs @ W2^T   [160,768] K=300 (fp32, 120 CTAs)
    sgemm32<<<dim3(5, 24), 256>>>(labe, En, W2, En, p_lab, Hn, Ln * LSn, Hn, En);
    // tkn = token @ W1^T (HMMA 3-pass, fp32 out + fp16 hi/lo split)
    tgemm<1,3><<<dim3(6, 16), 256, SMEM_SZ>>>(p_tokhi, p_toklo, Hn, p_W1hi, p_W1lo, Hn,
                                              p_tkn, Hn, nullptr);
    // T1 = tkn @ W5a^T (HMMA 3-pass)
    tgemm<0,3><<<dim3(6, 16), 256, SMEM_SZ>>>(p_tknhi, p_tknlo, Hn, p_W5ahi, p_W5alo, Hn,
                                              p_T1, Hn, nullptr);
    // Lab2 = lab @ W5b^T   [160,768] K=768 (fp32, 120 CTAs)
    sgemm32<<<dim3(5, 24), 256>>>(p_lab, Hn, W5 + Hn, 4 * Hn, p_Lab2, Hn, Ln * LSn, Hn, Hn);
    // scores = tkn @ lab^T [2048,160] K=768 (fp32, 320 CTAs)
    sgemm32<<<dim3(64, 5), 256>>>(p_tkn, Hn, p_lab, Hn, p_scores, Ln * LSn,
                                  BSn, Ln * LSn, Hn);
    // softmaxes
    softmax_a_kernel<<<MTOT / 256, 256>>>(lmask, imask);
    q2c_kernel<<<Bn * Ln, 256>>>();
    // fused A operand (fp16 hi/lo, l-major)
    afused_kernel<<<dim3(Ln, BSn / 16), 256>>>();
    // big fused GEMM (HMMA 2-pass) + epilogue
    tgemm<2,2><<<dim3(6, 320), 256, SMEM_SZ>>>(p_Afhi, p_Aflo, 2 * Hn, p_Bhi, p_Blo, 2 * Hn,
                                               out, 2 * Hn, b5);
}

// round 9
// speedup vs baseline: 8.2119x; 1.4311x over previous
#include <cuda_runtime.h>
#include <cuda_fp16.h>
#include <math.h>
#include <stdint.h>

// Problem dims
#define Bn   8
#define Sn   256
#define Hn   768
#define Ln   20
#define LSn  8
#define En   300
#define BSn  2048            // B*S
#define MTOT 40960           // B*S*L
#define NEGV (-10000.0f)

// ---------------- scratch (static device globals; no allocs allowed) ----------------
__device__ __align__(16) float g_tkn[BSn * Hn];
__device__ __align__(16) float g_T1[BSn * Hn];
__device__ __align__(16) float g_lab[Ln * LSn * Hn];
__device__ __align__(16) float g_Lab2[Ln * LSn * Hn];
__device__ __align__(16) float g_scores[BSn * Ln * LSn];
__device__ __align__(16) float g_a[MTOT * LSn];
__device__ __align__(16) float g_bin[MTOT];
__device__ __align__(16) float g_q2c[Bn * Ln * Hn];

__device__ __align__(16) __half g_tokhi[BSn * Hn];
__device__ __align__(16) __half g_toklo[BSn * Hn];
__device__ __align__(16) __half g_tknhi[BSn * Hn];
__device__ __align__(16) __half g_tknlo[BSn * Hn];
__device__ __align__(16) __half g_W1hi[Hn * Hn];
__device__ __align__(16) __half g_W1lo[Hn * Hn];
__device__ __align__(16) __half g_W5ahi[Hn * Hn];
__device__ __align__(16) __half g_W5alo[Hn * Hn];
__device__ __align__(16) __half g_Bhi[Hn * 2 * Hn];      // W5[c|d] as [768,1536], fp16 hi
// Af stored L-MAJOR: row m' = l*2048 + bs  (hi only — single-pass big GEMM)
__device__ __align__(16) __half g_Afhi[(size_t)MTOT * 1536];   // 126 MB

__device__ __forceinline__ uint32_t smem_u32(const void* p) {
    uint32_t a;
    asm("{ .reg .u64 t; cvta.to.shared.u64 t, %1; cvt.u32.u64 %0, t; }" : "=r"(a) : "l"(p));
    return a;
}

// fp16 round of a float4 -> packed 8B
__device__ __forceinline__ uint2 pack4(float4 v) {
    __half2 p0 = __halves2half2(__float2half_rn(v.x), __float2half_rn(v.y));
    __half2 p1 = __halves2half2(__float2half_rn(v.z), __float2half_rn(v.w));
    uint2 r;
    r.x = *reinterpret_cast<uint32_t*>(&p0);
    r.y = *reinterpret_cast<uint32_t*>(&p1);
    return r;
}

// SMEM: A stage0 @0, A stage1 @18432, B stage0 @36864, B stage1 @55296
#define STAGEB 18432              // 128*72*2 bytes (row padded to 144B)
#define SMEM_SZ 73728

// ---------------------------------------------------------------------------
// fp16-split MMA GEMM: C[M,N] = A[M,K] * B[N,K]^T
// PASS=3: Ahi*Bhi + Alo*Bhi + Ahi*Blo (error ~2^-22)
// PASS=1: Ahi*Bhi only               (error ~1.5e-4 realized; budget 1e-3)
// MODE 0: store fp32. MODE 1: fp32 + fp16 hi/lo split to g_tknhi/lo.
// MODE 2: A rows are l-major (m' = l*2048+bs); out[bs*20+l] =
//         tanh(acc + T1[bs] + sum_t a[m,t]*Lab2[l,t] + b5)
// ---------------------------------------------------------------------------
template <int MODE, int PASS>
__global__ __launch_bounds__(256, 2) void tgemm(
    const __half* __restrict__ Ahi, const __half* __restrict__ Alo, int lda,
    const __half* __restrict__ Bhi, const __half* __restrict__ Blo, int ldb,
    float* __restrict__ C, int Kd,
    const float* __restrict__ b5)
{
    extern __shared__ char smem[];
    const uint32_t sb = smem_u32(smem);
    const int tid = threadIdx.x;
    const int wid = tid >> 5, lid = tid & 31;
    const int n0 = blockIdx.x * 128, m0 = blockIdx.y * 128;

    const int wm = wid & 1;        // 0..1  -> 64-row slab
    const int wn = wid >> 1;       // 0..3  -> 32-col slab
    const int g  = lid >> 2;       // group id
    const int t4 = lid & 3;        // thread in group

    const int arow = wm * 64 + (lid & 15);
    const int acol = (lid >> 4) * 8;
    const int brow = wn * 32 + (lid & 7);
    const int bcol = ((lid >> 3) & 1) * 8;

    const int lrow = tid >> 3;
    const int lc8  = (tid & 7) * 8;

    const int NCp = Kd >> 6;
    const int NC  = NCp * PASS;

    float acc[4][4][4];
    #pragma unroll
    for (int i = 0; i < 4; i++)
        #pragma unroll
        for (int j = 0; j < 4; j++)
            #pragma unroll
            for (int r = 0; r < 4; r++) acc[i][j][r] = 0.0f;

    auto load_chunk = [&](int c, int s) {
        const int pass = (PASS == 1) ? 0 : ((c >= 2 * NCp) ? 2 : (c >= NCp ? 1 : 0));
        const int k0 = (c - pass * NCp) * 64;
        const __half* Ap = (pass == 1) ? Alo : Ahi;
        const __half* Bp = (pass == 2) ? Blo : Bhi;
        const uint32_t aB = sb + s * STAGEB;
        const uint32_t bB = sb + 36864 + s * STAGEB;
        #pragma unroll
        for (int p = 0; p < 4; p++) {
            const int row = lrow + p * 32;
            const uint32_t da = aB + (uint32_t)row * 144 + lc8 * 2;
            const void* ga = Ap + (size_t)(m0 + row) * lda + k0 + lc8;
            asm volatile("cp.async.cg.shared.global [%0], [%1], 16;" :: "r"(da), "l"(ga));
            const uint32_t db = bB + (uint32_t)row * 144 + lc8 * 2;
            const void* gb = Bp + (size_t)(n0 + row) * ldb + k0 + lc8;
            asm volatile("cp.async.cg.shared.global [%0], [%1], 16;" :: "r"(db), "l"(gb));
        }
        asm volatile("cp.async.commit_group;" ::: "memory");
    };

    auto compute = [&](int s) {
        const uint32_t aB = sb + s * STAGEB;
        const uint32_t bB = sb + 36864 + s * STAGEB;
        #pragma unroll
        for (int kk = 0; kk < 4; kk++) {
            uint32_t af[4][4], bf[4][2];
            #pragma unroll
            for (int i = 0; i < 4; i++) {
                const uint32_t ad = aB + (uint32_t)(arow + i * 16) * 144
                                  + (uint32_t)(kk * 16 + acol) * 2;
                asm volatile("ldmatrix.sync.aligned.m8n8.x4.shared.b16 {%0,%1,%2,%3}, [%4];"
                    : "=r"(af[i][0]), "=r"(af[i][1]), "=r"(af[i][2]), "=r"(af[i][3])
                    : "r"(ad));
            }
            #pragma unroll
            for (int j = 0; j < 4; j++) {
                const uint32_t bd = bB + (uint32_t)(brow + j * 8) * 144
                                  + (uint32_t)(kk * 16 + bcol) * 2;
                asm volatile("ldmatrix.sync.aligned.m8n8.x2.shared.b16 {%0,%1}, [%2];"
                    : "=r"(bf[j][0]), "=r"(bf[j][1]) : "r"(bd));
            }
            #pragma unroll
            for (int i = 0; i < 4; i++)
                #pragma unroll
                for (int j = 0; j < 4; j++)
                    asm volatile(
                        "mma.sync.aligned.m16n8k16.row.col.f32.f16.f16.f32 "
                        "{%0,%1,%2,%3}, {%4,%5,%6,%7}, {%8,%9}, {%0,%1,%2,%3};"
                        : "+f"(acc[i][j][0]), "+f"(acc[i][j][1]),
                          "+f"(acc[i][j][2]), "+f"(acc[i][j][3])
                        : "r"(af[i][0]), "r"(af[i][1]), "r"(af[i][2]), "r"(af[i][3]),
                          "r"(bf[j][0]), "r"(bf[j][1]));
        }
    };

    load_chunk(0, 0);
    for (int c = 0; c < NC; c++) {
        if (c + 1 < NC) {
            load_chunk(c + 1, (c + 1) & 1);
            asm volatile("cp.async.wait_group 1;" ::: "memory");
        } else {
            asm volatile("cp.async.wait_group 0;" ::: "memory");
        }
        __syncthreads();
        compute(c & 1);
        __syncthreads();
    }

    // ---------------- epilogue ----------------
    if (MODE == 2) {
        const int l   = m0 >> 11;        // 128 | 2048 so each tile is one l
        const int bsb = m0 & 2047;
        float* sLab = (float*)smem;          // [8][128]
        float* sB5  = sLab + 8 * 128;        // [128]
        float* sAv  = sB5 + 128;             // [128][8]
        for (int idx = tid; idx < 1024; idx += 256) {
            const int t = idx >> 7, o = idx & 127;
            sLab[idx] = g_Lab2[(size_t)(l * LSn + t) * Hn + n0 + o];
        }
        if (tid < 128) sB5[tid] = b5[n0 + tid];
        for (int idx = tid; idx < 1024; idx += 256) {
            const int r = idx >> 3, t = idx & 7;
            sAv[idx] = g_a[((size_t)(bsb + r) * Ln + l) * LSn + t];
        }
        __syncthreads();
        #pragma unroll
        for (int i = 0; i < 4; i++) {
            #pragma unroll
            for (int j = 0; j < 4; j++) {
                const int col = wn * 32 + j * 8 + 2 * t4;
                #pragma unroll
                for (int h = 0; h < 2; h++) {
                    const int rl = wm * 64 + i * 16 + g + h * 8;
                    const int bs = bsb + rl;
                    const float2 t1 = *(const float2*)(g_T1 + (size_t)bs * Hn + n0 + col);
                    float v0 = acc[i][j][h * 2]     + t1.x + sB5[col];
                    float v1 = acc[i][j][h * 2 + 1] + t1.y + sB5[col + 1];
                    const float* av = sAv + rl * 8;
                    #pragma unroll
                    for (int t = 0; t < 8; t++) {
                        const float at = av[t];
                        v0 += at * sLab[t * 128 + col];
                        v1 += at * sLab[t * 128 + col + 1];
                    }
                    float2 res = make_float2(tanhf(v0), tanhf(v1));
                    *(float2*)(C + ((size_t)bs * Ln + l) * Hn + n0 + col) = res;
                }
            }
        }
    } else {
        #pragma unroll
        for (int i = 0; i < 4; i++) {
            #pragma unroll
            for (int j = 0; j < 4; j++) {
                const int col = wn * 32 + j * 8 + 2 * t4;
                #pragma unroll
                for (int h = 0; h < 2; h++) {
                    const int m = m0 + wm * 64 + i * 16 + g + h * 8;
                    const float v0 = acc[i][j][h * 2];
                    const float v1 = acc[i][j][h * 2 + 1];
                    *(float2*)(C + (size_t)m * Hn + n0 + col) = make_float2(v0, v1);
                    if (MODE == 1) {
                        const size_t o = (size_t)m * Hn + n0 + col;
                        __half h0 = __float2half_rn(v0);
                        __half h1 = __float2half_rn(v1);
                        __half l0 = __float2half_rn(v0 - __half2float(h0));
                        __half l1 = __float2half_rn(v1 - __half2float(h1));
                        *(__half2*)(g_tknhi + o) = __halves2half2(h0, h1);
                        *(__half2*)(g_tknlo + o) = __halves2half2(l0, l1);
                    }
                }
            }
        }
    }
}

// ---------------------------------------------------------------------------
// fp32 -> fp16 hi/lo split (strided source)
// ---------------------------------------------------------------------------
__global__ __launch_bounds__(256) void split_k(
    const float* __restrict__ src, int ld,
    __half* __restrict__ hi, __half* __restrict__ lo,
    int Mr, int Kc)
{
    int idx = blockIdx.x * 256 + threadIdx.x;
    if (idx >= Mr * Kc) return;
    int r = idx / Kc, c = idx - r * Kc;
    float x = src[(size_t)r * ld + c];
    __half h = __float2half_rn(x);
    hi[idx] = h;
    if (lo) lo[idx] = __float2half_rn(x - __half2float(h));
}

// ---------------------------------------------------------------------------
// Small guarded SGEMM, 32x32 tile (high CTA count): C[M,N] = A[M,K]*B[N,K]^T
// ---------------------------------------------------------------------------
__global__ __launch_bounds__(256) void sgemm32(
    const float* __restrict__ A, int lda,
    const float* __restrict__ Bm, int ldb,
    float* __restrict__ C, int ldc,
    int M, int N, int K)
{
    __shared__ float As[32][33];
    __shared__ float Bs[32][33];
    const int m0 = blockIdx.x * 32;
    const int n0 = blockIdx.y * 32;
    const int tid = threadIdx.x;
    const int tr = tid >> 4;     // 0..15
    const int tc = tid & 15;     // 0..15
    float acc[2][2] = {};

    for (int k0 = 0; k0 < K; k0 += 32) {
        #pragma unroll
        for (int p = 0; p < 4; p++) {
            int idx = tid + p * 256;
            int r = idx >> 5;
            int kk = idx & 31;
            int gk = k0 + kk;
            int gm = m0 + r;
            int gn = n0 + r;
            As[kk][r] = (gm < M && gk < K) ? A[(size_t)gm * lda + gk] : 0.0f;
            Bs[kk][r] = (gn < N && gk < K) ? Bm[(size_t)gn * ldb + gk] : 0.0f;
        }
        __syncthreads();
        #pragma unroll
        for (int kk = 0; kk < 32; kk++) {
            float a0 = As[kk][tr * 2], a1 = As[kk][tr * 2 + 1];
            float b0 = Bs[kk][tc * 2], b1 = Bs[kk][tc * 2 + 1];
            acc[0][0] += a0 * b0; acc[0][1] += a0 * b1;
            acc[1][0] += a1 * b0; acc[1][1] += a1 * b1;
        }
        __syncthreads();
    }
    #pragma unroll
    for (int i = 0; i < 2; i++) {
        int gm = m0 + tr * 2 + i;
        if (gm >= M) continue;
        #pragma unroll
        for (int j = 0; j < 2; j++) {
            int gn = n0 + tc * 2 + j;
            if (gn < N) C[(size_t)gm * ldc + gn] = acc[i][j];
        }
    }
}

// ---------------------------------------------------------------------------
// Softmax over label tokens + b_in
// ---------------------------------------------------------------------------
__global__ __launch_bounds__(256) void softmax_a_kernel(
    const float* __restrict__ label_mask,
    const float* __restrict__ input_mask)
{
    int m = blockIdx.x * 256 + threadIdx.x;
    if (m >= MTOT) return;
    int bs = m / Ln;
    int l = m - bs * Ln;
    float sc[LSn];
    float mx = -INFINITY;
    #pragma unroll
    for (int t = 0; t < LSn; t++) {
        float v = g_scores[(size_t)bs * (Ln * LSn) + l * LSn + t]
                + (1.0f - label_mask[l * LSn + t]) * NEGV;
        sc[t] = v;
        mx = fmaxf(mx, v);
    }
    float sum = 0.0f;
    #pragma unroll
    for (int t = 0; t < LSn; t++) { sc[t] = __expf(sc[t] - mx); sum += sc[t]; }
    float inv = 1.0f / sum;
    #pragma unroll
    for (int t = 0; t < LSn; t++) g_a[(size_t)m * LSn + t] = sc[t] * inv;
    g_bin[m] = mx + (1.0f - input_mask[bs]) * NEGV;
}

// ---------------------------------------------------------------------------
// Softmax over S + q2c
// ---------------------------------------------------------------------------
__global__ __launch_bounds__(256) void q2c_kernel()
{
    int b = blockIdx.x / Ln;
    int l = blockIdx.x - b * Ln;
    int s = threadIdx.x;
    __shared__ float red[256];
    __shared__ float w[256];

    float v = g_bin[(size_t)(b * Sn + s) * Ln + l];
    red[s] = v; __syncthreads();
    for (int off = 128; off > 0; off >>= 1) {
        if (s < off) red[s] = fmaxf(red[s], red[s + off]);
        __syncthreads();
    }
    float mx = red[0]; __syncthreads();
    float e = __expf(v - mx);
    red[s] = e; __syncthreads();
    for (int off = 128; off > 0; off >>= 1) {
        if (s < off) red[s] += red[s + off];
        __syncthreads();
    }
    float inv = 1.0f / red[0];
    w[s] = e * inv;
    __syncthreads();

    for (int h = s; h < Hn; h += 256) {
        float acc = 0.0f;
        #pragma unroll 8
        for (int ss = 0; ss < Sn; ss++)
            acc += w[ss] * g_tkn[(size_t)(b * Sn + ss) * Hn + h];
        g_q2c[(size_t)(b * Ln + l) * Hn + h] = acc;
    }
}

// ---------------------------------------------------------------------------
// Build fused A operand as fp16 (hi only), L-MAJOR rows (m' = l*2048+bs):
//   Af[m', h]      = tkn*c2q   (h in [0,768))
//   Af[m', 768+h]  = tkn*q2c
// ---------------------------------------------------------------------------
__global__ __launch_bounds__(256) void afused_kernel()
{
    int l   = blockIdx.x;
    int bs0 = blockIdx.y * 16;
    int b   = bs0 / Sn;
    int tid = threadIdx.x;

    __shared__ float labs[LSn * Hn];
    __shared__ float qv[Hn];
    __shared__ float av[16][LSn];

    for (int idx = tid; idx < LSn * Hn; idx += 256)
        labs[idx] = g_lab[(size_t)l * LSn * Hn + idx];
    for (int idx = tid; idx < Hn; idx += 256)
        qv[idx] = g_q2c[(size_t)(b * Ln + l) * Hn + idx];
    for (int idx = tid; idx < 16 * LSn; idx += 256) {
        int i = idx >> 3, t = idx & 7;
        av[i][t] = g_a[((size_t)(bs0 + i) * Ln + l) * LSn + t];
    }
    __syncthreads();

    const int hc = tid * 4;          // threads 0..191 active (192*4 = 768)
    for (int i = 0; i < 16; i++) {
        int bs = bs0 + i;
        size_t m = (size_t)l * BSn + bs;     // l-major row
        if (hc < Hn) {
            float a0 = av[i][0], a1 = av[i][1], a2 = av[i][2], a3 = av[i][3];
            float a4 = av[i][4], a5 = av[i][5], a6 = av[i][6], a7 = av[i][7];
            const float4 tv = *(const float4*)(g_tkn + (size_t)bs * Hn + hc);
            const float4 qv4 = *(const float4*)(qv + hc);
            float4 c = make_float4(0.f, 0.f, 0.f, 0.f);
            #pragma unroll
            for (int t = 0; t < LSn; t++) {
                const float at = (t == 0) ? a0 : (t == 1) ? a1 : (t == 2) ? a2 :
                                 (t == 3) ? a3 : (t == 4) ? a4 : (t == 5) ? a5 :
                                 (t == 6) ? a6 : a7;
                const float4 lb = *(const float4*)(labs + t * Hn + hc);
                c.x += at * lb.x; c.y += at * lb.y;
                c.z += at * lb.z; c.w += at * lb.w;
            }
            float4 v1 = make_float4(tv.x * c.x, tv.y * c.y, tv.z * c.z, tv.w * c.w);
            float4 v2 = make_float4(tv.x * qv4.x, tv.y * qv4.y, tv.z * qv4.z, tv.w * qv4.w);
            __half* Ah = g_Afhi + m * 1536;
            *(uint2*)(Ah + hc)      = pack4(v1);
            *(uint2*)(Ah + Hn + hc) = pack4(v2);
        }
    }
}

// ---------------------------------------------------------------------------
extern "C" void kernel_launch(void* const* d_in, const int* in_sizes, int n_in,
                              void* d_out, int out_size)
{
    const float* token = (const float*)d_in[0];
    const float* labe  = (const float*)d_in[1];
    const float* imask = (const float*)d_in[2];
    const float* lmask = (const float*)d_in[3];
    const float* W1    = (const float*)d_in[4];
    const float* W2    = (const float*)d_in[5];
    const float* W5    = (const float*)d_in[6];
    const float* b5    = (const float*)d_in[7];
    float* out = (float*)d_out;

    float *p_tkn, *p_lab, *p_T1, *p_Lab2, *p_scores;
    __half *p_tokhi, *p_toklo, *p_tknhi, *p_tknlo;
    __half *p_W1hi, *p_W1lo, *p_W5ahi, *p_W5alo, *p_Bhi, *p_Afhi;
    cudaGetSymbolAddress((void**)&p_tkn,    g_tkn);
    cudaGetSymbolAddress((void**)&p_lab,    g_lab);
    cudaGetSymbolAddress((void**)&p_T1,     g_T1);
    cudaGetSymbolAddress((void**)&p_Lab2,   g_Lab2);
    cudaGetSymbolAddress((void**)&p_scores, g_scores);
    cudaGetSymbolAddress((void**)&p_tokhi,  g_tokhi);
    cudaGetSymbolAddress((void**)&p_toklo,  g_toklo);
    cudaGetSymbolAddress((void**)&p_tknhi,  g_tknhi);
    cudaGetSymbolAddress((void**)&p_tknlo,  g_tknlo);
    cudaGetSymbolAddress((void**)&p_W1hi,   g_W1hi);
    cudaGetSymbolAddress((void**)&p_W1lo,   g_W1lo);
    cudaGetSymbolAddress((void**)&p_W5ahi,  g_W5ahi);
    cudaGetSymbolAddress((void**)&p_W5alo,  g_W5alo);
    cudaGetSymbolAddress((void**)&p_Bhi,    g_Bhi);
    cudaGetSymbolAddress((void**)&p_Afhi,   g_Afhi);

    cudaFuncSetAttribute((const void*)tgemm<0,3>, cudaFuncAttributeMaxDynamicSharedMemorySize, SMEM_SZ);
    cudaFuncSetAttribute((const void*)tgemm<1,3>, cudaFuncAttributeMaxDynamicSharedMemorySize, SMEM_SZ);
    cudaFuncSetAttribute((const void*)tgemm<2,1>, cudaFuncAttributeMaxDynamicSharedMemorySize, SMEM_SZ);

    // splits (fp16 hi/lo; W5cd hi-only)
    split_k<<<(BSn * Hn + 255) / 256, 256>>>(token, Hn, p_tokhi, p_toklo, BSn, Hn);
    split_k<<<(Hn * Hn + 255) / 256, 256>>>(W1, Hn, p_W1hi, p_W1lo, Hn, Hn);
    split_k<<<(Hn * Hn + 255) / 256, 256>>>(W5, 4 * Hn, p_W5ahi, p_W5alo, Hn, Hn);
    split_k<<<(Hn * 2 * Hn + 255) / 256, 256>>>(W5 + 2 * Hn, 4 * Hn, p_Bhi, (__half*)nullptr, Hn, 2 * Hn);

    // lab = label_embs @ W2^T   [160,768] K=300 (fp32, 120 CTAs)
    sgemm32<<<dim3(5, 24), 256>>>(labe, En, W2, En, p_lab, Hn, Ln * LSn, Hn, En);
    // tkn = token @ W1^T (HMMA 3-pass, fp32 out + fp16 hi/lo split)
    tgemm<1,3><<<dim3(6, 16), 256, SMEM_SZ>>>(p_tokhi, p_toklo, Hn, p_W1hi, p_W1lo, Hn,
                                              p_tkn, Hn, nullptr);
    // T1 = tkn @ W5a^T (HMMA 3-pass)
    tgemm<0,3><<<dim3(6, 16), 256, SMEM_SZ>>>(p_tknhi, p_tknlo, Hn, p_W5ahi, p_W5alo, Hn,
                                              p_T1, Hn, nullptr);
    // Lab2 = lab @ W5b^T   [160,768] K=768 (fp32, 120 CTAs)
    sgemm32<<<dim3(5, 24), 256>>>(p_lab, Hn, W5 + Hn, 4 * Hn, p_Lab2, Hn, Ln * LSn, Hn, Hn);
    // scores = tkn @ lab^T [2048,160] K=768 (fp32, 320 CTAs)
    sgemm32<<<dim3(64, 5), 256>>>(p_tkn, Hn, p_lab, Hn, p_scores, Ln * LSn,
                                  BSn, Ln * LSn, Hn);
    // softmaxes
    softmax_a_kernel<<<MTOT / 256, 256>>>(lmask, imask);
    q2c_kernel<<<Bn * Ln, 256>>>();
    // fused A operand (fp16 hi, l-major)
    afused_kernel<<<dim3(Ln, BSn / 16), 256>>>();
    // big fused GEMM (HMMA single-pass) + epilogue
    tgemm<2,1><<<dim3(6, 320), 256, SMEM_SZ>>>(p_Afhi, (const __half*)nullptr, 2 * Hn,
                                               p_Bhi, (const __half*)nullptr, 2 * Hn,
                                               out, 2 * Hn, b5);
}